// round 2
// baseline (speedup 1.0000x reference)
#include <cuda_runtime.h>

#define BS   2048
#define HD   1024
#define NE   8
#define FF   512
#define TWOF 1024
#define EPSV 1e-9f

// ---------------- device scratch (static, allocation-free) ----------------
__device__ int   g_valid_cnt[NE];
__device__ int   g_mis_cnt[NE];
__device__ int   g_expert_cnt[NE];
__device__ int   g_expert_tok[NE][BS];   // packed token*2 + k
__device__ float g_expert_w[NE][BS];
__device__ int   g_sel[BS][2];
__device__ float g_rw[BS][2];
__device__ float g_wfinal[BS][2];
__device__ float g_act[NE][BS][FF];      // 32 MB
__device__ float g_partial[BS][2][HD];   // 16 MB

// ---------------- K0: zero counters ----------------
__global__ void k_zero() {
    int i = threadIdx.x;
    if (i < NE) { g_valid_cnt[i] = 0; g_mis_cnt[i] = 0; g_expert_cnt[i] = 0; }
}

// ---------------- K1: router GEMM + softmax + top2 + modality counts ----------------
__global__ void __launch_bounds__(256) k_router(
    const float* __restrict__ x, const float* __restrict__ gw,
    const int* __restrict__ tmod, const int* __restrict__ emod)
{
    __shared__ float sgw[NE * HD];   // 32 KB
    for (int i = threadIdx.x; i < NE * HD; i += blockDim.x) sgw[i] = gw[i];
    __syncthreads();

    int warp = threadIdx.x >> 5, lane = threadIdx.x & 31;
    int gwid = blockIdx.x * 8 + warp;   // 32 blocks * 8 warps = 256 warps

    for (int t = gwid; t < BS; t += 256) {
        const float* xr = x + (size_t)t * HD;
        float acc[NE];
        #pragma unroll
        for (int e = 0; e < NE; e++) acc[e] = 0.f;
        for (int h = lane; h < HD; h += 32) {
            float xv = xr[h];
            #pragma unroll
            for (int e = 0; e < NE; e++) acc[e] = fmaf(xv, sgw[e * HD + h], acc[e]);
        }
        #pragma unroll
        for (int e = 0; e < NE; e++) {
            #pragma unroll
            for (int o = 16; o > 0; o >>= 1) acc[e] += __shfl_xor_sync(0xffffffffu, acc[e], o);
        }
        if (lane == 0) {
            float m = acc[0];
            #pragma unroll
            for (int e = 1; e < NE; e++) m = fmaxf(m, acc[e]);
            float p[NE], s = 0.f;
            #pragma unroll
            for (int e = 0; e < NE; e++) { p[e] = __expf(acc[e] - m); s += p[e]; }
            float inv = 1.f / s;
            #pragma unroll
            for (int e = 0; e < NE; e++) p[e] *= inv;
            // top-2 (descending, lowest index on ties — matches jax.lax.top_k)
            int i1 = 0; float m1 = p[0];
            #pragma unroll
            for (int e = 1; e < NE; e++) if (p[e] > m1) { m1 = p[e]; i1 = e; }
            int i2 = -1; float m2 = -1.f;
            #pragma unroll
            for (int e = 0; e < NE; e++) if (e != i1 && p[e] > m2) { m2 = p[e]; i2 = e; }
            float inv2 = 1.f / (m1 + m2);
            g_sel[t][0] = i1; g_sel[t][1] = i2;
            g_rw[t][0] = m1 * inv2; g_rw[t][1] = m2 * inv2;
            int tm = tmod[t];
            int sel2[2] = { i1, i2 };
            #pragma unroll
            for (int k = 0; k < 2; k++) {
                int e = sel2[k];
                int em = emod[e];
                bool valid = (tm != 0) && (em != 0);
                if (valid) {
                    atomicAdd(&g_valid_cnt[e], 1);
                    if (tm * em == -1) atomicAdd(&g_mis_cnt[e], 1);
                }
            }
        }
    }
}

// ---------------- K2: skip mask, renorm, build per-expert lists ----------------
__global__ void k_assign(const int* __restrict__ emod) {
    int t = blockIdx.x * blockDim.x + threadIdx.x;
    if (t >= BS) return;
    bool skip[NE];
    #pragma unroll
    for (int e = 0; e < NE; e++) {
        int vc = g_valid_cnt[e], mc = g_mis_cnt[e];
        skip[e] = (vc > 0) && (mc == vc) && (emod[e] != 0);
    }
    int s0 = g_sel[t][0], s1 = g_sel[t][1];
    float w0 = g_rw[t][0], w1 = g_rw[t][1];
    if (skip[s0]) w0 = 0.f;
    if (skip[s1]) w1 = 0.f;
    float sum = w0 + w1;
    if (sum > 0.f) { float inv = 1.f / fmaxf(sum, EPSV); w0 *= inv; w1 *= inv; }
    g_wfinal[t][0] = w0; g_wfinal[t][1] = w1;
    if (w0 > 0.f) {
        int p = atomicAdd(&g_expert_cnt[s0], 1);
        g_expert_tok[s0][p] = t * 2;     g_expert_w[s0][p] = w0;
    }
    if (w1 > 0.f) {
        int p = atomicAdd(&g_expert_cnt[s1], 1);
        g_expert_tok[s1][p] = t * 2 + 1; g_expert_w[s1][p] = w1;
    }
}

// ---------------- K3a: gathered GEMM1 (x @ gate_up) fused SiLU*u -> act ----------------
// grid: (8 ftile, 32 mtile, 8 expert), block 256. Tile: 64 tokens x 128 cols (64 g + 64 u).
__global__ void __launch_bounds__(256) k_gemm1(
    const float* __restrict__ x, const float* __restrict__ gup)
{
    int e = blockIdx.z;
    int count = g_expert_cnt[e];
    int m0 = blockIdx.y * 64;
    if (m0 >= count) return;
    int f0 = blockIdx.x * 64;

    __shared__ int   ts[64];
    __shared__ float smem[64 * 128];     // reused: Xs[64][17] + Ws[16][128], then Cs[64][128]
    float* Xs = smem;                    // 1088 floats
    float* Ws = smem + 1104;             // 16B aligned

    if (threadIdx.x < 64) {
        int s = m0 + threadIdx.x;
        ts[threadIdx.x] = (s < count) ? (g_expert_tok[e][s] >> 1) : 0;
    }
    __syncthreads();

    const float* W = gup + (size_t)e * HD * TWOF;
    int tid = threadIdx.x, tx = tid & 31, ty = tid >> 5;
    float acc[8][4];
    #pragma unroll
    for (int m = 0; m < 8; m++)
        #pragma unroll
        for (int n = 0; n < 4; n++) acc[m][n] = 0.f;

    for (int kb = 0; kb < HD; kb += 16) {
        #pragma unroll
        for (int i = 0; i < 4; i++) {
            int idx = tid + i * 256;
            int r = idx >> 4, c = idx & 15;
            Xs[r * 17 + c] = x[(size_t)ts[r] * HD + kb + c];
        }
        #pragma unroll
        for (int i = 0; i < 8; i++) {
            int idx = tid + i * 256;
            int r = idx >> 7, c = idx & 127;
            int n = (c < 64) ? (f0 + c) : (448 + f0 + c);   // g half / u half
            Ws[r * 128 + c] = W[(size_t)(kb + r) * TWOF + n];
        }
        __syncthreads();
        #pragma unroll
        for (int kk = 0; kk < 16; kk++) {
            float4 bv = *(const float4*)&Ws[kk * 128 + tx * 4];
            #pragma unroll
            for (int m = 0; m < 8; m++) {
                float a = Xs[(ty * 8 + m) * 17 + kk];
                acc[m][0] = fmaf(a, bv.x, acc[m][0]);
                acc[m][1] = fmaf(a, bv.y, acc[m][1]);
                acc[m][2] = fmaf(a, bv.z, acc[m][2]);
                acc[m][3] = fmaf(a, bv.w, acc[m][3]);
            }
        }
        __syncthreads();
    }
    // stash C in smem, then fused SiLU(g)*u
    float* Cs = smem;
    #pragma unroll
    for (int m = 0; m < 8; m++) {
        float4 v = make_float4(acc[m][0], acc[m][1], acc[m][2], acc[m][3]);
        *(float4*)&Cs[(ty * 8 + m) * 128 + tx * 4] = v;
    }
    __syncthreads();
    #pragma unroll
    for (int i = 0; i < 16; i++) {
        int idx = tid + i * 256;
        int r = idx >> 6, j = idx & 63;
        int s = m0 + r;
        if (s < count) {
            float g = Cs[r * 128 + j];
            float u = Cs[r * 128 + 64 + j];
            float a = g / (1.f + __expf(-g)) * u;
            g_act[e][s][f0 + j] = a;
        }
    }
}

// ---------------- K3b: GEMM2 (act @ down), weighted write to partial ----------------
// grid: (8 ntile, 32 mtile, 8 expert), block 256. Tile: 64 x 128.
__global__ void __launch_bounds__(256) k_gemm2(const float* __restrict__ down)
{
    int e = blockIdx.z;
    int count = g_expert_cnt[e];
    int m0 = blockIdx.y * 64;
    if (m0 >= count) return;
    int n0 = blockIdx.x * 128;

    __shared__ float As[64 * 17];
    __shared__ float Bs[16 * 128];
    __shared__ int   tsp[64];
    __shared__ float tw[64];

    if (threadIdx.x < 64) {
        int s = m0 + threadIdx.x;
        tsp[threadIdx.x] = (s < count) ? g_expert_tok[e][s] : -1;
        tw[threadIdx.x]  = (s < count) ? g_expert_w[e][s] : 0.f;
    }
    __syncthreads();

    const float* W = down + (size_t)e * FF * HD;
    int tid = threadIdx.x, tx = tid & 31, ty = tid >> 5;
    float acc[8][4];
    #pragma unroll
    for (int m = 0; m < 8; m++)
        #pragma unroll
        for (int n = 0; n < 4; n++) acc[m][n] = 0.f;

    for (int kb = 0; kb < FF; kb += 16) {
        #pragma unroll
        for (int i = 0; i < 4; i++) {
            int idx = tid + i * 256;
            int r = idx >> 4, c = idx & 15;
            int s = m0 + r;
            As[r * 17 + c] = (s < count) ? g_act[e][s][kb + c] : 0.f;
        }
        #pragma unroll
        for (int i = 0; i < 8; i++) {
            int idx = tid + i * 256;
            int r = idx >> 7, c = idx & 127;
            Bs[r * 128 + c] = W[(size_t)(kb + r) * HD + n0 + c];
        }
        __syncthreads();
        #pragma unroll
        for (int kk = 0; kk < 16; kk++) {
            float4 bv = *(const float4*)&Bs[kk * 128 + tx * 4];
            #pragma unroll
            for (int m = 0; m < 8; m++) {
                float a = As[(ty * 8 + m) * 17 + kk];
                acc[m][0] = fmaf(a, bv.x, acc[m][0]);
                acc[m][1] = fmaf(a, bv.y, acc[m][1]);
                acc[m][2] = fmaf(a, bv.z, acc[m][2]);
                acc[m][3] = fmaf(a, bv.w, acc[m][3]);
            }
        }
        __syncthreads();
    }
    #pragma unroll
    for (int m = 0; m < 8; m++) {
        int r = ty * 8 + m;
        int packed = tsp[r];
        if (packed >= 0) {
            float w = tw[r];
            float4 v = make_float4(acc[m][0] * w, acc[m][1] * w, acc[m][2] * w, acc[m][3] * w);
            float* dst = &g_partial[0][0][0] + (size_t)packed * HD + n0 + tx * 4;
            *(float4*)dst = v;
        }
    }
}

// ---------------- K4: combine slots -> out ----------------
__global__ void k_combine(float* __restrict__ out) {
    int i = blockIdx.x * blockDim.x + threadIdx.x;   // float4 index
    if (i >= BS * HD / 4) return;
    int t = i >> 8;          // 256 float4 per token row
    int c = i & 255;
    float w0 = g_wfinal[t][0], w1 = g_wfinal[t][1];
    float4 r = make_float4(0.f, 0.f, 0.f, 0.f);
    if (w0 > 0.f) {
        float4 a = *(const float4*)&g_partial[t][0][c * 4];
        r.x += a.x; r.y += a.y; r.z += a.z; r.w += a.w;
    }
    if (w1 > 0.f) {
        float4 b = *(const float4*)&g_partial[t][1][c * 4];
        r.x += b.x; r.y += b.y; r.z += b.z; r.w += b.w;
    }
    ((float4*)out)[i] = r;
}

// ---------------- launch ----------------
extern "C" void kernel_launch(void* const* d_in, const int* in_sizes, int n_in,
                              void* d_out, int out_size)
{
    const float* x    = (const float*)d_in[0];   // [2,1024,1024]
    const float* gw   = (const float*)d_in[1];   // [8,1024]
    const float* gup  = (const float*)d_in[2];   // [8,1024,1024]
    const float* down = (const float*)d_in[3];   // [8,512,1024]
    const int*   tmod = (const int*)d_in[4];     // [2048]
    const int*   emod = (const int*)d_in[5];     // [8]
    float* out = (float*)d_out;                  // [2,1024,1024]

    k_zero<<<1, 32>>>();
    k_router<<<32, 256>>>(x, gw, tmod, emod);
    k_assign<<<8, 256>>>(emod);
    k_gemm1<<<dim3(8, 32, 8), 256>>>(x, gup);
    k_gemm2<<<dim3(8, 32, 8), 256>>>(down);
    k_combine<<<(BS * HD / 4 + 255) / 256, 256>>>(out);
}

// round 4
// speedup vs baseline: 2.5292x; 2.5292x over previous
#include <cuda_runtime.h>

#define BS   2048
#define HD   1024
#define NE   8
#define FF   512
#define TWOF 1024
#define EPSV 1e-9f

// ======================= device scratch =======================
__device__ int   g_valid_cnt[NE];
__device__ int   g_mis_cnt[NE];
__device__ int   g_expert_cnt[NE];
__device__ int   g_expert_tok[NE][BS];     // packed token*2 + k
__device__ float g_expert_w[NE][BS];
__device__ int   g_sel[BS][2];
__device__ float g_rw[BS][2];
__device__ float g_wfinal[BS][2];
__device__ float g_W1T[NE][TWOF][HD];      // gate_up^T (tf32-rounded)
__device__ float g_W2T[NE][HD][FF];        // down^T    (tf32-rounded)
__device__ float g_xg[NE][BS][HD];         // gathered tokens (tf32-rounded, zero padded)
__device__ float g_act[NE][BS][FF];        // silu(g)*u (tf32-rounded)
__device__ float g_partial[BS][2][HD];     // weighted partials

// ======================= PTX helpers (sm_80+ family-portable only) =======================
__device__ __forceinline__ unsigned smem_u32(const void* p) {
    unsigned a;
    asm("{ .reg .u64 t; cvta.to.shared.u64 t, %1; cvt.u32.u64 %0, t; }" : "=r"(a) : "l"(p));
    return a;
}
__device__ __forceinline__ float tf32r(float x) {
    float r;
    asm("cvt.rna.tf32.f32 %0, %1;" : "=f"(r) : "f"(x));
    return r;
}
#define CP16(s, g) asm volatile("cp.async.cg.shared.global [%0], [%1], 16;" :: "r"(s), "l"(g))
#define CPCOMMIT() asm volatile("cp.async.commit_group;" ::: "memory")
#define CPWAIT(n)  asm volatile("cp.async.wait_group %0;" :: "n"(n) : "memory")
#define LDSM4(r0, r1, r2, r3, a) \
    asm volatile("ldmatrix.sync.aligned.m8n8.x4.shared.b16 {%0,%1,%2,%3}, [%4];" \
        : "=r"(r0), "=r"(r1), "=r"(r2), "=r"(r3) : "r"(a))
#define MMA8(c, a0, a1, a2, a3, b0, b1) \
    asm volatile("mma.sync.aligned.m16n8k8.row.col.f32.tf32.tf32.f32 " \
        "{%0,%1,%2,%3}, {%4,%5,%6,%7}, {%8,%9}, {%0,%1,%2,%3};" \
        : "+f"((c)[0]), "+f"((c)[1]), "+f"((c)[2]), "+f"((c)[3]) \
        : "r"(a0), "r"(a1), "r"(a2), "r"(a3), "r"(b0), "r"(b1))

// dynamic smem layout for MMA kernels: [0,512) tsp ints, [512,1024) tw floats,
// A(s) = 1024 + s*32768, B(s) = A(s) + 16384  (2 stages, 128x32 f32 tiles)
#define SMM_A(s) (1024 + (s) * 32768)
#define SMM_B(s) (1024 + (s) * 32768 + 16384)
#define SMM_BYTES (1024 + 2 * 32768)   // 66560

// ======================= K0: zero counters =======================
__global__ void k_zero() {
    int i = threadIdx.x;
    if (i < NE) { g_valid_cnt[i] = 0; g_mis_cnt[i] = 0; g_expert_cnt[i] = 0; }
}

// ======================= K1: router =======================
__global__ void __launch_bounds__(256) k_router(
    const float* __restrict__ x, const float* __restrict__ gw,
    const int* __restrict__ tmod, const int* __restrict__ emod)
{
    __shared__ float sgw[NE * HD];
    for (int i = threadIdx.x; i < NE * HD; i += blockDim.x) sgw[i] = gw[i];
    __syncthreads();
    int warp = threadIdx.x >> 5, lane = threadIdx.x & 31;
    int gwid = blockIdx.x * 8 + warp;
    for (int t = gwid; t < BS; t += 256) {
        const float* xr = x + (size_t)t * HD;
        float acc[NE];
        #pragma unroll
        for (int e = 0; e < NE; e++) acc[e] = 0.f;
        for (int h = lane; h < HD; h += 32) {
            float xv = xr[h];
            #pragma unroll
            for (int e = 0; e < NE; e++) acc[e] = fmaf(xv, sgw[e * HD + h], acc[e]);
        }
        #pragma unroll
        for (int e = 0; e < NE; e++) {
            #pragma unroll
            for (int o = 16; o > 0; o >>= 1) acc[e] += __shfl_xor_sync(0xffffffffu, acc[e], o);
        }
        if (lane == 0) {
            float m = acc[0];
            #pragma unroll
            for (int e = 1; e < NE; e++) m = fmaxf(m, acc[e]);
            float p[NE], s = 0.f;
            #pragma unroll
            for (int e = 0; e < NE; e++) { p[e] = __expf(acc[e] - m); s += p[e]; }
            float inv = 1.f / s;
            #pragma unroll
            for (int e = 0; e < NE; e++) p[e] *= inv;
            int i1 = 0; float m1 = p[0];
            #pragma unroll
            for (int e = 1; e < NE; e++) if (p[e] > m1) { m1 = p[e]; i1 = e; }
            int i2 = -1; float m2 = -1.f;
            #pragma unroll
            for (int e = 0; e < NE; e++) if (e != i1 && p[e] > m2) { m2 = p[e]; i2 = e; }
            float inv2 = 1.f / (m1 + m2);
            g_sel[t][0] = i1; g_sel[t][1] = i2;
            g_rw[t][0] = m1 * inv2; g_rw[t][1] = m2 * inv2;
            int tm = tmod[t];
            int sel2[2] = { i1, i2 };
            #pragma unroll
            for (int k = 0; k < 2; k++) {
                int e = sel2[k];
                int em = emod[e];
                if (tm != 0 && em != 0) {
                    atomicAdd(&g_valid_cnt[e], 1);
                    if (tm * em == -1) atomicAdd(&g_mis_cnt[e], 1);
                }
            }
        }
    }
}

// ======================= K2: assign =======================
__global__ void k_assign(const int* __restrict__ emod) {
    int t = blockIdx.x * blockDim.x + threadIdx.x;
    if (t >= BS) return;
    bool skip[NE];
    #pragma unroll
    for (int e = 0; e < NE; e++) {
        int vc = g_valid_cnt[e], mc = g_mis_cnt[e];
        skip[e] = (vc > 0) && (mc == vc) && (emod[e] != 0);
    }
    int s0 = g_sel[t][0], s1 = g_sel[t][1];
    float w0 = g_rw[t][0], w1 = g_rw[t][1];
    if (skip[s0]) w0 = 0.f;
    if (skip[s1]) w1 = 0.f;
    float sum = w0 + w1;
    if (sum > 0.f) { float inv = 1.f / fmaxf(sum, EPSV); w0 *= inv; w1 *= inv; }
    g_wfinal[t][0] = w0; g_wfinal[t][1] = w1;
    if (w0 > 0.f) {
        int p = atomicAdd(&g_expert_cnt[s0], 1);
        g_expert_tok[s0][p] = t * 2;     g_expert_w[s0][p] = w0;
    }
    if (w1 > 0.f) {
        int p = atomicAdd(&g_expert_cnt[s1], 1);
        g_expert_tok[s1][p] = t * 2 + 1; g_expert_w[s1][p] = w1;
    }
}

// ======================= K3: weight transposes (with tf32 rounding) =======================
__global__ void __launch_bounds__(256) k_tr1(const float* __restrict__ gup) {
    __shared__ float tile[32][33];
    int e = blockIdx.z;
    int kt = blockIdx.x * 32, nt = blockIdx.y * 32;
    const float* src = gup + (size_t)e * HD * TWOF;
    float* dst = &g_W1T[e][0][0];
    int tx = threadIdx.x, ty = threadIdx.y;
    #pragma unroll
    for (int i = 0; i < 32; i += 8)
        tile[ty + i][tx] = src[(size_t)(kt + ty + i) * TWOF + nt + tx];
    __syncthreads();
    #pragma unroll
    for (int i = 0; i < 32; i += 8)
        dst[(size_t)(nt + ty + i) * HD + kt + tx] = tf32r(tile[tx][ty + i]);
}
__global__ void __launch_bounds__(256) k_tr2(const float* __restrict__ down) {
    __shared__ float tile[32][33];
    int e = blockIdx.z;
    int kt = blockIdx.x * 32, nt = blockIdx.y * 32;
    const float* src = down + (size_t)e * FF * HD;
    float* dst = &g_W2T[e][0][0];
    int tx = threadIdx.x, ty = threadIdx.y;
    #pragma unroll
    for (int i = 0; i < 32; i += 8)
        tile[ty + i][tx] = src[(size_t)(kt + ty + i) * HD + nt + tx];
    __syncthreads();
    #pragma unroll
    for (int i = 0; i < 32; i += 8)
        dst[(size_t)(nt + ty + i) * FF + kt + tx] = tf32r(tile[tx][ty + i]);
}

// ======================= K4: gather tokens (tf32-rounded, zero-padded to 128) =======================
__global__ void __launch_bounds__(256) k_gather(const float* __restrict__ x) {
    int e = blockIdx.y;
    int s = blockIdx.x;
    int count = g_expert_cnt[e];
    int padded = (count + 127) & ~127;
    if (s >= padded) return;
    float4* dst = (float4*)&g_xg[e][s][0];
    if (s < count) {
        int t = g_expert_tok[e][s] >> 1;
        float4 v = ((const float4*)(x + (size_t)t * HD))[threadIdx.x];
        v.x = tf32r(v.x); v.y = tf32r(v.y); v.z = tf32r(v.z); v.w = tf32r(v.w);
        dst[threadIdx.x] = v;
    } else {
        dst[threadIdx.x] = make_float4(0.f, 0.f, 0.f, 0.f);
    }
}

// ======================= K5: GEMM1 tf32 mma.sync + fused SiLU*u =======================
// CTA tile 128(M) x 128(N internal: 64 g + 64 u), BK=32, 8 warps (warp tile 16x128)
// grid (FF/64 = 8, 16, NE)
__global__ void __launch_bounds__(256, 2) k_mma1() {
    int e = blockIdx.z;
    int count = g_expert_cnt[e];
    int m0 = blockIdx.y * 128;
    if (m0 >= count) return;
    int f0 = blockIdx.x * 64;

    extern __shared__ char sm[];
    unsigned sb = smem_u32(sm);
    int tid = threadIdx.x, lane = tid & 31, w = tid >> 5;

    const float* Ab = &g_xg[e][m0][0];
    const float* Wb = &g_W1T[e][0][0];

    // per-thread staging coords
    const float* ga[4]; const float* gb[4]; unsigned soff[4];
    #pragma unroll
    for (int i = 0; i < 4; i++) {
        int idx = tid + i * 256;
        int r = idx >> 3, c = idx & 7;
        ga[i] = Ab + (size_t)r * HD + c * 4;
        int rowg = f0 + r + ((r >= 64) ? 448 : 0);
        gb[i] = Wb + (size_t)rowg * HD + c * 4;
        soff[i] = r * 128 + ((c ^ (r & 7)) << 4);
    }

    float acc[16][4];
    #pragma unroll
    for (int f = 0; f < 16; f++)
        #pragma unroll
        for (int q = 0; q < 4; q++) acc[f][q] = 0.f;

    // ldmatrix address components
    int l7 = lane & 7, hi = lane >> 4, bsel = (lane >> 3) & 3;
    unsigned arow = sb + (w * 16 + (lane & 15)) * 128;       // + SMM_A(s)
    unsigned brow = sb + ((lane & 7) * 128);                  // + SMM_B(s) + f*1024

    // prologue: stage 0
    #pragma unroll
    for (int i = 0; i < 4; i++) {
        CP16(sb + SMM_A(0) + soff[i], ga[i]);
        CP16(sb + SMM_B(0) + soff[i], gb[i]);
    }
    CPCOMMIT();

    const int NK = HD / 32;
    for (int kb = 0; kb < NK; kb++) {
        int s = kb & 1;
        if (kb + 1 < NK) {
            int ns = s ^ 1;
            #pragma unroll
            for (int i = 0; i < 4; i++) {
                CP16(sb + SMM_A(ns) + soff[i], ga[i] + (kb + 1) * 32);
                CP16(sb + SMM_B(ns) + soff[i], gb[i] + (kb + 1) * 32);
            }
            CPCOMMIT();
            CPWAIT(1);
        } else {
            CPWAIT(0);
        }
        __syncthreads();

        unsigned sA = arow + SMM_A(s);
        unsigned sB = brow + SMM_B(s);
        #pragma unroll
        for (int kh = 0; kh < 2; kh++) {
            unsigned a0, a1, a2, a3, a4, a5, a6, a7;
            LDSM4(a0, a1, a2, a3, sA + (((4 * kh + 0 + hi) ^ l7) << 4));
            LDSM4(a4, a5, a6, a7, sA + (((4 * kh + 2 + hi) ^ l7) << 4));
            unsigned cb = (((4 * kh + bsel) ^ l7) << 4);
            #pragma unroll
            for (int f = 0; f < 16; f++) {
                unsigned b0, b1, b2, b3;
                LDSM4(b0, b1, b2, b3, sB + f * 1024 + cb);
                MMA8(acc[f], a0, a1, a2, a3, b0, b1);
                MMA8(acc[f], a4, a5, a6, a7, b2, b3);
            }
        }
        __syncthreads();
    }

    // epilogue: silu(g)*u in registers (frag f = g col j, frag f+8 = u col j+64)
    int p = lane & 3, rlo = lane >> 2;
    int slot0 = m0 + w * 16 + rlo, slot1 = slot0 + 8;
    #pragma unroll
    for (int f = 0; f < 8; f++) {
        int j = f * 8 + 2 * p;
        if (slot0 < count) {
            float g0 = acc[f][0], g1 = acc[f][1];
            float u0 = acc[f + 8][0], u1 = acc[f + 8][1];
            float v0 = tf32r(g0 / (1.f + __expf(-g0)) * u0);
            float v1 = tf32r(g1 / (1.f + __expf(-g1)) * u1);
            *(float2*)&g_act[e][slot0][f0 + j] = make_float2(v0, v1);
        }
        if (slot1 < count) {
            float g0 = acc[f][2], g1 = acc[f][3];
            float u0 = acc[f + 8][2], u1 = acc[f + 8][3];
            float v0 = tf32r(g0 / (1.f + __expf(-g0)) * u0);
            float v1 = tf32r(g1 / (1.f + __expf(-g1)) * u1);
            *(float2*)&g_act[e][slot1][f0 + j] = make_float2(v0, v1);
        }
    }
}

// ======================= K6: GEMM2 tf32 mma.sync, weighted scatter =======================
// CTA tile 128(M) x 128(N), BK=32, grid (HD/128 = 8, 16, NE)
__global__ void __launch_bounds__(256, 2) k_mma2() {
    int e = blockIdx.z;
    int count = g_expert_cnt[e];
    int m0 = blockIdx.y * 128;
    if (m0 >= count) return;
    int n0 = blockIdx.x * 128;

    extern __shared__ char sm[];
    unsigned sb = smem_u32(sm);
    int tid = threadIdx.x, lane = tid & 31, w = tid >> 5;

    int*   tsp = (int*)sm;
    float* tw  = (float*)(sm + 512);
    if (tid < 128) {
        int s = m0 + tid;
        tsp[tid] = (s < count) ? g_expert_tok[e][s] : -1;
        tw[tid]  = (s < count) ? g_expert_w[e][s] : 0.f;
    }

    const float* Ab = &g_act[e][m0][0];
    const float* Wb = &g_W2T[e][n0][0];

    const float* ga[4]; const float* gb[4]; unsigned soff[4];
    #pragma unroll
    for (int i = 0; i < 4; i++) {
        int idx = tid + i * 256;
        int r = idx >> 3, c = idx & 7;
        ga[i] = Ab + (size_t)r * FF + c * 4;
        gb[i] = Wb + (size_t)r * FF + c * 4;
        soff[i] = r * 128 + ((c ^ (r & 7)) << 4);
    }

    float acc[16][4];
    #pragma unroll
    for (int f = 0; f < 16; f++)
        #pragma unroll
        for (int q = 0; q < 4; q++) acc[f][q] = 0.f;

    int l7 = lane & 7, hi = lane >> 4, bsel = (lane >> 3) & 3;
    unsigned arow = sb + (w * 16 + (lane & 15)) * 128;
    unsigned brow = sb + ((lane & 7) * 128);

    #pragma unroll
    for (int i = 0; i < 4; i++) {
        CP16(sb + SMM_A(0) + soff[i], ga[i]);
        CP16(sb + SMM_B(0) + soff[i], gb[i]);
    }
    CPCOMMIT();

    const int NK = FF / 32;
    for (int kb = 0; kb < NK; kb++) {
        int s = kb & 1;
        if (kb + 1 < NK) {
            int ns = s ^ 1;
            #pragma unroll
            for (int i = 0; i < 4; i++) {
                CP16(sb + SMM_A(ns) + soff[i], ga[i] + (kb + 1) * 32);
                CP16(sb + SMM_B(ns) + soff[i], gb[i] + (kb + 1) * 32);
            }
            CPCOMMIT();
            CPWAIT(1);
        } else {
            CPWAIT(0);
        }
        __syncthreads();

        unsigned sA = arow + SMM_A(s);
        unsigned sB = brow + SMM_B(s);
        #pragma unroll
        for (int kh = 0; kh < 2; kh++) {
            unsigned a0, a1, a2, a3, a4, a5, a6, a7;
            LDSM4(a0, a1, a2, a3, sA + (((4 * kh + 0 + hi) ^ l7) << 4));
            LDSM4(a4, a5, a6, a7, sA + (((4 * kh + 2 + hi) ^ l7) << 4));
            unsigned cb = (((4 * kh + bsel) ^ l7) << 4);
            #pragma unroll
            for (int f = 0; f < 16; f++) {
                unsigned b0, b1, b2, b3;
                LDSM4(b0, b1, b2, b3, sB + f * 1024 + cb);
                MMA8(acc[f], a0, a1, a2, a3, b0, b1);
                MMA8(acc[f], a4, a5, a6, a7, b2, b3);
            }
        }
        __syncthreads();
    }

    // epilogue: weighted scatter
    int p = lane & 3, rlo = lane >> 2;
    int r0i = w * 16 + rlo, r1i = r0i + 8;
    int pk0 = tsp[r0i], pk1 = tsp[r1i];
    float wt0 = tw[r0i], wt1 = tw[r1i];
    #pragma unroll
    for (int f = 0; f < 16; f++) {
        int j = f * 8 + 2 * p;
        if (pk0 >= 0) {
            float* dst = &g_partial[0][0][0] + (size_t)pk0 * HD + n0 + j;
            *(float2*)dst = make_float2(acc[f][0] * wt0, acc[f][1] * wt0);
        }
        if (pk1 >= 0) {
            float* dst = &g_partial[0][0][0] + (size_t)pk1 * HD + n0 + j;
            *(float2*)dst = make_float2(acc[f][2] * wt1, acc[f][3] * wt1);
        }
    }
}

// ======================= K7: combine =======================
__global__ void k_combine(float* __restrict__ out) {
    int i = blockIdx.x * blockDim.x + threadIdx.x;
    if (i >= BS * HD / 4) return;
    int t = i >> 8;
    int c = i & 255;
    float w0 = g_wfinal[t][0], w1 = g_wfinal[t][1];
    float4 r = make_float4(0.f, 0.f, 0.f, 0.f);
    if (w0 > 0.f) {
        float4 a = *(const float4*)&g_partial[t][0][c * 4];
        r.x += a.x; r.y += a.y; r.z += a.z; r.w += a.w;
    }
    if (w1 > 0.f) {
        float4 b = *(const float4*)&g_partial[t][1][c * 4];
        r.x += b.x; r.y += b.y; r.z += b.z; r.w += b.w;
    }
    ((float4*)out)[i] = r;
}

// ======================= launch =======================
extern "C" void kernel_launch(void* const* d_in, const int* in_sizes, int n_in,
                              void* d_out, int out_size)
{
    const float* x    = (const float*)d_in[0];
    const float* gw   = (const float*)d_in[1];
    const float* gup  = (const float*)d_in[2];
    const float* down = (const float*)d_in[3];
    const int*   tmod = (const int*)d_in[4];
    const int*   emod = (const int*)d_in[5];
    float* out = (float*)d_out;

    cudaFuncSetAttribute(k_mma1, cudaFuncAttributeMaxDynamicSharedMemorySize, SMM_BYTES);
    cudaFuncSetAttribute(k_mma2, cudaFuncAttributeMaxDynamicSharedMemorySize, SMM_BYTES);

    k_zero<<<1, 32>>>();
    k_tr1<<<dim3(32, 32, NE), dim3(32, 8)>>>(gup);
    k_tr2<<<dim3(16, 32, NE), dim3(32, 8)>>>(down);
    k_router<<<32, 256>>>(x, gw, tmod, emod);
    k_assign<<<8, 256>>>(emod);
    k_gather<<<dim3(BS, NE), 256>>>(x);
    k_mma1<<<dim3(8, 16, NE), 256, SMM_BYTES>>>();
    k_mma2<<<dim3(8, 16, NE), 256, SMM_BYTES>>>();
    k_combine<<<(BS * HD / 4 + 255) / 256, 256>>>(out);
}

// round 5
// speedup vs baseline: 3.0962x; 1.2242x over previous
#include <cuda_runtime.h>

#define BS   2048
#define HD   1024
#define NE   8
#define FF   512
#define TWOF 1024
#define EPSV 1e-9f

// ======================= device scratch =======================
__device__ int   g_valid_cnt[NE];
__device__ int   g_mis_cnt[NE];
__device__ int   g_expert_cnt[NE];
__device__ int   g_expert_tok[NE][BS];     // packed token*2 + k
__device__ float g_expert_w[NE][BS];
__device__ int   g_sel[BS][2];
__device__ float g_rw[BS][2];
__device__ float g_wfinal[BS][2];
__device__ float g_W1T[NE][TWOF][HD];      // gate_up^T (tf32-rounded)
__device__ float g_W2T[NE][HD][FF];        // down^T    (tf32-rounded)
__device__ float g_xg[NE][BS][HD];         // gathered tokens (tf32-rounded, zero padded)
__device__ float g_act[NE][BS][FF];        // silu(g)*u (tf32-rounded)
__device__ float g_partial[BS][2][HD];     // weighted partials

// ======================= PTX helpers (sm_80+ family-portable only) =======================
__device__ __forceinline__ unsigned smem_u32(const void* p) {
    unsigned a;
    asm("{ .reg .u64 t; cvta.to.shared.u64 t, %1; cvt.u32.u64 %0, t; }" : "=r"(a) : "l"(p));
    return a;
}
__device__ __forceinline__ float tf32r(float x) {
    float r;
    asm("cvt.rna.tf32.f32 %0, %1;" : "=f"(r) : "f"(x));
    return r;
}
#define CP16(s, g) asm volatile("cp.async.cg.shared.global [%0], [%1], 16;" :: "r"(s), "l"(g))
#define CPCOMMIT() asm volatile("cp.async.commit_group;" ::: "memory")
#define CPWAIT(n)  asm volatile("cp.async.wait_group %0;" :: "n"(n) : "memory")
#define LDSM4(r0, r1, r2, r3, a) \
    asm volatile("ldmatrix.sync.aligned.m8n8.x4.shared.b16 {%0,%1,%2,%3}, [%4];" \
        : "=r"(r0), "=r"(r1), "=r"(r2), "=r"(r3) : "r"(a))
#define MMA8(c, a0, a1, a2, a3, b0, b1) \
    asm volatile("mma.sync.aligned.m16n8k8.row.col.f32.tf32.tf32.f32 " \
        "{%0,%1,%2,%3}, {%4,%5,%6,%7}, {%8,%9}, {%0,%1,%2,%3};" \
        : "+f"((c)[0]), "+f"((c)[1]), "+f"((c)[2]), "+f"((c)[3]) \
        : "r"(a0), "r"(a1), "r"(a2), "r"(a3), "r"(b0), "r"(b1))

// dynamic smem layout for MMA kernels
#define SMM_A(s) (1024 + (s) * 32768)
#define SMM_B(s) (1024 + (s) * 32768 + 16384)
#define SMM_BYTES (1024 + 2 * 32768)   // 66560

// ======================= K0: zero counters =======================
__global__ void k_zero() {
    int i = threadIdx.x;
    if (i < NE) { g_valid_cnt[i] = 0; g_mis_cnt[i] = 0; g_expert_cnt[i] = 0; }
}

// ======================= K1: router — one warp per token, float4 loads =======================
__global__ void __launch_bounds__(256) k_router(
    const float* __restrict__ x, const float* __restrict__ gw,
    const int* __restrict__ tmod, const int* __restrict__ emod)
{
    __shared__ float sgw[NE * HD];   // 32 KB
    for (int i = threadIdx.x; i < NE * HD / 4; i += blockDim.x)
        *(float4*)&sgw[i * 4] = ((const float4*)gw)[i];
    __syncthreads();

    int warp = threadIdx.x >> 5, lane = threadIdx.x & 31;
    int t = blockIdx.x * 8 + warp;           // 256 blocks * 8 warps = 2048 warps = BS
    if (t >= BS) return;

    const float4* xr = (const float4*)(x + (size_t)t * HD);
    float acc[NE];
    #pragma unroll
    for (int e = 0; e < NE; e++) acc[e] = 0.f;
    #pragma unroll
    for (int i = 0; i < 8; i++) {
        int q = lane + i * 32;               // float4 index within row (256 total)
        float4 xv = xr[q];
        #pragma unroll
        for (int e = 0; e < NE; e++) {
            const float4 wv = *(const float4*)&sgw[e * HD + q * 4];
            acc[e] = fmaf(xv.x, wv.x, acc[e]);
            acc[e] = fmaf(xv.y, wv.y, acc[e]);
            acc[e] = fmaf(xv.z, wv.z, acc[e]);
            acc[e] = fmaf(xv.w, wv.w, acc[e]);
        }
    }
    #pragma unroll
    for (int e = 0; e < NE; e++) {
        #pragma unroll
        for (int o = 16; o > 0; o >>= 1) acc[e] += __shfl_xor_sync(0xffffffffu, acc[e], o);
    }
    if (lane == 0) {
        float m = acc[0];
        #pragma unroll
        for (int e = 1; e < NE; e++) m = fmaxf(m, acc[e]);
        float p[NE], s = 0.f;
        #pragma unroll
        for (int e = 0; e < NE; e++) { p[e] = __expf(acc[e] - m); s += p[e]; }
        float inv = 1.f / s;
        #pragma unroll
        for (int e = 0; e < NE; e++) p[e] *= inv;
        int i1 = 0; float m1 = p[0];
        #pragma unroll
        for (int e = 1; e < NE; e++) if (p[e] > m1) { m1 = p[e]; i1 = e; }
        int i2 = -1; float m2 = -1.f;
        #pragma unroll
        for (int e = 0; e < NE; e++) if (e != i1 && p[e] > m2) { m2 = p[e]; i2 = e; }
        float inv2 = 1.f / (m1 + m2);
        g_sel[t][0] = i1; g_sel[t][1] = i2;
        g_rw[t][0] = m1 * inv2; g_rw[t][1] = m2 * inv2;
        int tm = tmod[t];
        int sel2[2] = { i1, i2 };
        #pragma unroll
        for (int k = 0; k < 2; k++) {
            int e = sel2[k];
            int em = emod[e];
            if (tm != 0 && em != 0) {
                atomicAdd(&g_valid_cnt[e], 1);
                if (tm * em == -1) atomicAdd(&g_mis_cnt[e], 1);
            }
        }
    }
}

// ======================= K2: assign =======================
__global__ void k_assign(const int* __restrict__ emod) {
    int t = blockIdx.x * blockDim.x + threadIdx.x;
    if (t >= BS) return;
    bool skip[NE];
    #pragma unroll
    for (int e = 0; e < NE; e++) {
        int vc = g_valid_cnt[e], mc = g_mis_cnt[e];
        skip[e] = (vc > 0) && (mc == vc) && (emod[e] != 0);
    }
    int s0 = g_sel[t][0], s1 = g_sel[t][1];
    float w0 = g_rw[t][0], w1 = g_rw[t][1];
    if (skip[s0]) w0 = 0.f;
    if (skip[s1]) w1 = 0.f;
    float sum = w0 + w1;
    if (sum > 0.f) { float inv = 1.f / fmaxf(sum, EPSV); w0 *= inv; w1 *= inv; }
    g_wfinal[t][0] = w0; g_wfinal[t][1] = w1;
    if (w0 > 0.f) {
        int p = atomicAdd(&g_expert_cnt[s0], 1);
        g_expert_tok[s0][p] = t * 2;     g_expert_w[s0][p] = w0;
    }
    if (w1 > 0.f) {
        int p = atomicAdd(&g_expert_cnt[s1], 1);
        g_expert_tok[s1][p] = t * 2 + 1; g_expert_w[s1][p] = w1;
    }
}

// ======================= K3: weight transposes (with tf32 rounding) =======================
__global__ void __launch_bounds__(256) k_tr1(const float* __restrict__ gup) {
    __shared__ float tile[32][33];
    int e = blockIdx.z;
    int kt = blockIdx.x * 32, nt = blockIdx.y * 32;
    const float* src = gup + (size_t)e * HD * TWOF;
    float* dst = &g_W1T[e][0][0];
    int tx = threadIdx.x, ty = threadIdx.y;
    #pragma unroll
    for (int i = 0; i < 32; i += 8)
        tile[ty + i][tx] = src[(size_t)(kt + ty + i) * TWOF + nt + tx];
    __syncthreads();
    #pragma unroll
    for (int i = 0; i < 32; i += 8)
        dst[(size_t)(nt + ty + i) * HD + kt + tx] = tf32r(tile[tx][ty + i]);
}
__global__ void __launch_bounds__(256) k_tr2(const float* __restrict__ down) {
    __shared__ float tile[32][33];
    int e = blockIdx.z;
    int kt = blockIdx.x * 32, nt = blockIdx.y * 32;
    const float* src = down + (size_t)e * FF * HD;
    float* dst = &g_W2T[e][0][0];
    int tx = threadIdx.x, ty = threadIdx.y;
    #pragma unroll
    for (int i = 0; i < 32; i += 8)
        tile[ty + i][tx] = src[(size_t)(kt + ty + i) * HD + nt + tx];
    __syncthreads();
    #pragma unroll
    for (int i = 0; i < 32; i += 8)
        dst[(size_t)(nt + ty + i) * FF + kt + tx] = tf32r(tile[tx][ty + i]);
}

// ======================= K4: gather tokens (tf32-rounded, zero-padded to 128) =======================
__global__ void __launch_bounds__(256) k_gather(const float* __restrict__ x) {
    int e = blockIdx.y;
    int s = blockIdx.x;
    int count = g_expert_cnt[e];
    int padded = (count + 127) & ~127;
    if (s >= padded) return;
    float4* dst = (float4*)&g_xg[e][s][0];
    if (s < count) {
        int t = g_expert_tok[e][s] >> 1;
        float4 v = ((const float4*)(x + (size_t)t * HD))[threadIdx.x];
        v.x = tf32r(v.x); v.y = tf32r(v.y); v.z = tf32r(v.z); v.w = tf32r(v.w);
        dst[threadIdx.x] = v;
    } else {
        dst[threadIdx.x] = make_float4(0.f, 0.f, 0.f, 0.f);
    }
}

// ======================= K5: GEMM1 tf32 mma.sync + fused SiLU*u =======================
__global__ void __launch_bounds__(256, 2) k_mma1() {
    int e = blockIdx.z;
    int count = g_expert_cnt[e];
    int m0 = blockIdx.y * 128;
    if (m0 >= count) return;
    int f0 = blockIdx.x * 64;

    extern __shared__ char sm[];
    unsigned sb = smem_u32(sm);
    int tid = threadIdx.x, lane = tid & 31, w = tid >> 5;

    const float* Ab = &g_xg[e][m0][0];
    const float* Wb = &g_W1T[e][0][0];

    const float* ga[4]; const float* gb[4]; unsigned soff[4];
    #pragma unroll
    for (int i = 0; i < 4; i++) {
        int idx = tid + i * 256;
        int r = idx >> 3, c = idx & 7;
        ga[i] = Ab + (size_t)r * HD + c * 4;
        int rowg = f0 + r + ((r >= 64) ? 448 : 0);
        gb[i] = Wb + (size_t)rowg * HD + c * 4;
        soff[i] = r * 128 + ((c ^ (r & 7)) << 4);
    }

    float acc[16][4];
    #pragma unroll
    for (int f = 0; f < 16; f++)
        #pragma unroll
        for (int q = 0; q < 4; q++) acc[f][q] = 0.f;

    int l7 = lane & 7, hi = lane >> 4, bsel = (lane >> 3) & 3;
    unsigned arow = sb + (w * 16 + (lane & 15)) * 128;
    unsigned brow = sb + ((lane & 7) * 128);

    #pragma unroll
    for (int i = 0; i < 4; i++) {
        CP16(sb + SMM_A(0) + soff[i], ga[i]);
        CP16(sb + SMM_B(0) + soff[i], gb[i]);
    }
    CPCOMMIT();

    const int NK = HD / 32;
    for (int kb = 0; kb < NK; kb++) {
        int s = kb & 1;
        if (kb + 1 < NK) {
            int ns = s ^ 1;
            #pragma unroll
            for (int i = 0; i < 4; i++) {
                CP16(sb + SMM_A(ns) + soff[i], ga[i] + (kb + 1) * 32);
                CP16(sb + SMM_B(ns) + soff[i], gb[i] + (kb + 1) * 32);
            }
            CPCOMMIT();
            CPWAIT(1);
        } else {
            CPWAIT(0);
        }
        __syncthreads();

        unsigned sA = arow + SMM_A(s);
        unsigned sB = brow + SMM_B(s);
        #pragma unroll
        for (int kh = 0; kh < 2; kh++) {
            unsigned a0, a1, a2, a3, a4, a5, a6, a7;
            LDSM4(a0, a1, a2, a3, sA + (((4 * kh + 0 + hi) ^ l7) << 4));
            LDSM4(a4, a5, a6, a7, sA + (((4 * kh + 2 + hi) ^ l7) << 4));
            unsigned cb = (((4 * kh + bsel) ^ l7) << 4);
            #pragma unroll
            for (int f = 0; f < 16; f++) {
                unsigned b0, b1, b2, b3;
                LDSM4(b0, b1, b2, b3, sB + f * 1024 + cb);
                MMA8(acc[f], a0, a1, a2, a3, b0, b1);
                MMA8(acc[f], a4, a5, a6, a7, b2, b3);
            }
        }
        __syncthreads();
    }

    int p = lane & 3, rlo = lane >> 2;
    int slot0 = m0 + w * 16 + rlo, slot1 = slot0 + 8;
    #pragma unroll
    for (int f = 0; f < 8; f++) {
        int j = f * 8 + 2 * p;
        if (slot0 < count) {
            float g0 = acc[f][0], g1 = acc[f][1];
            float u0 = acc[f + 8][0], u1 = acc[f + 8][1];
            float v0 = tf32r(g0 / (1.f + __expf(-g0)) * u0);
            float v1 = tf32r(g1 / (1.f + __expf(-g1)) * u1);
            *(float2*)&g_act[e][slot0][f0 + j] = make_float2(v0, v1);
        }
        if (slot1 < count) {
            float g0 = acc[f][2], g1 = acc[f][3];
            float u0 = acc[f + 8][2], u1 = acc[f + 8][3];
            float v0 = tf32r(g0 / (1.f + __expf(-g0)) * u0);
            float v1 = tf32r(g1 / (1.f + __expf(-g1)) * u1);
            *(float2*)&g_act[e][slot1][f0 + j] = make_float2(v0, v1);
        }
    }
}

// ======================= K6: GEMM2 tf32 mma.sync, weighted scatter =======================
__global__ void __launch_bounds__(256, 2) k_mma2() {
    int e = blockIdx.z;
    int count = g_expert_cnt[e];
    int m0 = blockIdx.y * 128;
    if (m0 >= count) return;
    int n0 = blockIdx.x * 128;

    extern __shared__ char sm[];
    unsigned sb = smem_u32(sm);
    int tid = threadIdx.x, lane = tid & 31, w = tid >> 5;

    int*   tsp = (int*)sm;
    float* tw  = (float*)(sm + 512);
    if (tid < 128) {
        int s = m0 + tid;
        tsp[tid] = (s < count) ? g_expert_tok[e][s] : -1;
        tw[tid]  = (s < count) ? g_expert_w[e][s] : 0.f;
    }

    const float* Ab = &g_act[e][m0][0];
    const float* Wb = &g_W2T[e][n0][0];

    const float* ga[4]; const float* gb[4]; unsigned soff[4];
    #pragma unroll
    for (int i = 0; i < 4; i++) {
        int idx = tid + i * 256;
        int r = idx >> 3, c = idx & 7;
        ga[i] = Ab + (size_t)r * FF + c * 4;
        gb[i] = Wb + (size_t)r * FF + c * 4;
        soff[i] = r * 128 + ((c ^ (r & 7)) << 4);
    }

    float acc[16][4];
    #pragma unroll
    for (int f = 0; f < 16; f++)
        #pragma unroll
        for (int q = 0; q < 4; q++) acc[f][q] = 0.f;

    int l7 = lane & 7, hi = lane >> 4, bsel = (lane >> 3) & 3;
    unsigned arow = sb + (w * 16 + (lane & 15)) * 128;
    unsigned brow = sb + ((lane & 7) * 128);

    #pragma unroll
    for (int i = 0; i < 4; i++) {
        CP16(sb + SMM_A(0) + soff[i], ga[i]);
        CP16(sb + SMM_B(0) + soff[i], gb[i]);
    }
    CPCOMMIT();

    const int NK = FF / 32;
    for (int kb = 0; kb < NK; kb++) {
        int s = kb & 1;
        if (kb + 1 < NK) {
            int ns = s ^ 1;
            #pragma unroll
            for (int i = 0; i < 4; i++) {
                CP16(sb + SMM_A(ns) + soff[i], ga[i] + (kb + 1) * 32);
                CP16(sb + SMM_B(ns) + soff[i], gb[i] + (kb + 1) * 32);
            }
            CPCOMMIT();
            CPWAIT(1);
        } else {
            CPWAIT(0);
        }
        __syncthreads();

        unsigned sA = arow + SMM_A(s);
        unsigned sB = brow + SMM_B(s);
        #pragma unroll
        for (int kh = 0; kh < 2; kh++) {
            unsigned a0, a1, a2, a3, a4, a5, a6, a7;
            LDSM4(a0, a1, a2, a3, sA + (((4 * kh + 0 + hi) ^ l7) << 4));
            LDSM4(a4, a5, a6, a7, sA + (((4 * kh + 2 + hi) ^ l7) << 4));
            unsigned cb = (((4 * kh + bsel) ^ l7) << 4);
            #pragma unroll
            for (int f = 0; f < 16; f++) {
                unsigned b0, b1, b2, b3;
                LDSM4(b0, b1, b2, b3, sB + f * 1024 + cb);
                MMA8(acc[f], a0, a1, a2, a3, b0, b1);
                MMA8(acc[f], a4, a5, a6, a7, b2, b3);
            }
        }
        __syncthreads();
    }

    int p = lane & 3, rlo = lane >> 2;
    int r0i = w * 16 + rlo, r1i = r0i + 8;
    int pk0 = tsp[r0i], pk1 = tsp[r1i];
    float wt0 = tw[r0i], wt1 = tw[r1i];
    #pragma unroll
    for (int f = 0; f < 16; f++) {
        int j = f * 8 + 2 * p;
        if (pk0 >= 0) {
            float* dst = &g_partial[0][0][0] + (size_t)pk0 * HD + n0 + j;
            *(float2*)dst = make_float2(acc[f][0] * wt0, acc[f][1] * wt0);
        }
        if (pk1 >= 0) {
            float* dst = &g_partial[0][0][0] + (size_t)pk1 * HD + n0 + j;
            *(float2*)dst = make_float2(acc[f][2] * wt1, acc[f][3] * wt1);
        }
    }
}

// ======================= K7: combine =======================
__global__ void k_combine(float* __restrict__ out) {
    int i = blockIdx.x * blockDim.x + threadIdx.x;
    if (i >= BS * HD / 4) return;
    int t = i >> 8;
    int c = i & 255;
    float w0 = g_wfinal[t][0], w1 = g_wfinal[t][1];
    float4 r = make_float4(0.f, 0.f, 0.f, 0.f);
    if (w0 > 0.f) {
        float4 a = *(const float4*)&g_partial[t][0][c * 4];
        r.x += a.x; r.y += a.y; r.z += a.z; r.w += a.w;
    }
    if (w1 > 0.f) {
        float4 b = *(const float4*)&g_partial[t][1][c * 4];
        r.x += b.x; r.y += b.y; r.z += b.z; r.w += b.w;
    }
    ((float4*)out)[i] = r;
}

// ======================= launch =======================
extern "C" void kernel_launch(void* const* d_in, const int* in_sizes, int n_in,
                              void* d_out, int out_size)
{
    const float* x    = (const float*)d_in[0];
    const float* gw   = (const float*)d_in[1];
    const float* gup  = (const float*)d_in[2];
    const float* down = (const float*)d_in[3];
    const int*   tmod = (const int*)d_in[4];
    const int*   emod = (const int*)d_in[5];
    float* out = (float*)d_out;

    cudaFuncSetAttribute(k_mma1, cudaFuncAttributeMaxDynamicSharedMemorySize, SMM_BYTES);
    cudaFuncSetAttribute(k_mma2, cudaFuncAttributeMaxDynamicSharedMemorySize, SMM_BYTES);

    k_zero<<<1, 32>>>();
    k_tr1<<<dim3(32, 32, NE), dim3(32, 8)>>>(gup);
    k_tr2<<<dim3(16, 32, NE), dim3(32, 8)>>>(down);
    k_router<<<256, 256>>>(x, gw, tmod, emod);
    k_assign<<<8, 256>>>(emod);
    k_gather<<<dim3(BS, NE), 256>>>(x);
    k_mma1<<<dim3(8, 16, NE), 256, SMM_BYTES>>>();
    k_mma2<<<dim3(8, 16, NE), 256, SMM_BYTES>>>();
    k_combine<<<(BS * HD / 4 + 255) / 256, 256>>>(out);
}

// round 6
// speedup vs baseline: 3.6329x; 1.1733x over previous
#include <cuda_runtime.h>

#define BS   2048
#define HD   1024
#define NE   8
#define FF   512
#define TWOF 1024
#define EPSV 1e-9f

// ======================= device scratch =======================
__device__ int   g_valid_cnt[NE];
__device__ int   g_mis_cnt[NE];
__device__ int   g_expert_cnt[NE];
__device__ int   g_expert_tok[NE][BS];     // packed token*2 + k
__device__ float g_expert_w[NE][BS];
__device__ int   g_sel[BS][2];
__device__ float g_rw[BS][2];
__device__ float g_wfinal[BS][2];
__device__ float g_xr[BS][HD];             // tf32-rounded x (8 MB)
__device__ float g_W1T[NE][TWOF][HD];      // gate_up^T (tf32-rounded)
__device__ float g_W2T[NE][HD][FF];        // down^T    (tf32-rounded)
__device__ float g_act[NE][BS][FF];        // silu(g)*u (tf32-rounded)
__device__ float g_partial[BS][2][HD];     // weighted partials

// ======================= PTX helpers (sm_80+ family-portable only) =======================
__device__ __forceinline__ unsigned smem_u32(const void* p) {
    unsigned a;
    asm("{ .reg .u64 t; cvta.to.shared.u64 t, %1; cvt.u32.u64 %0, t; }" : "=r"(a) : "l"(p));
    return a;
}
__device__ __forceinline__ float tf32r(float x) {
    float r;
    asm("cvt.rna.tf32.f32 %0, %1;" : "=f"(r) : "f"(x));
    return r;
}
#define CP16(s, g) asm volatile("cp.async.cg.shared.global [%0], [%1], 16;" :: "r"(s), "l"(g))
#define CPCOMMIT() asm volatile("cp.async.commit_group;" ::: "memory")
#define CPWAIT(n)  asm volatile("cp.async.wait_group %0;" :: "n"(n) : "memory")
#define LDSM4(r0, r1, r2, r3, a) \
    asm volatile("ldmatrix.sync.aligned.m8n8.x4.shared.b16 {%0,%1,%2,%3}, [%4];" \
        : "=r"(r0), "=r"(r1), "=r"(r2), "=r"(r3) : "r"(a))
#define MMA8(c, a0, a1, a2, a3, b0, b1) \
    asm volatile("mma.sync.aligned.m16n8k8.row.col.f32.tf32.tf32.f32 " \
        "{%0,%1,%2,%3}, {%4,%5,%6,%7}, {%8,%9}, {%0,%1,%2,%3};" \
        : "+f"((c)[0]), "+f"((c)[1]), "+f"((c)[2]), "+f"((c)[3]) \
        : "r"(a0), "r"(a1), "r"(a2), "r"(a3), "r"(b0), "r"(b1))

// dynamic smem layout for MMA kernels
#define SMM_A(s) (1024 + (s) * 32768)
#define SMM_B(s) (1024 + (s) * 32768 + 16384)
#define SMM_BYTES (1024 + 2 * 32768)   // 66560

// ======================= K_prep: fused transposes + counter zero =======================
__global__ void __launch_bounds__(256) k_prep(
    const float* __restrict__ gup, const float* __restrict__ down)
{
    __shared__ float tile[32][33];
    int e = blockIdx.z;
    int tx = threadIdx.x, ty = threadIdx.y;
    if (blockIdx.x == 0 && blockIdx.y == 0 && e == 0 && ty == 0 && tx < NE) {
        g_valid_cnt[tx] = 0; g_mis_cnt[tx] = 0; g_expert_cnt[tx] = 0;
    }
    if (blockIdx.y < 32) {
        int kt = blockIdx.x * 32, nt = blockIdx.y * 32;
        const float* src = gup + (size_t)e * HD * TWOF;
        float* dst = &g_W1T[e][0][0];
        #pragma unroll
        for (int i = 0; i < 32; i += 8)
            tile[ty + i][tx] = src[(size_t)(kt + ty + i) * TWOF + nt + tx];
        __syncthreads();
        #pragma unroll
        for (int i = 0; i < 32; i += 8)
            dst[(size_t)(nt + ty + i) * HD + kt + tx] = tf32r(tile[tx][ty + i]);
    } else {
        int kt = (blockIdx.y - 32) * 32, nt = blockIdx.x * 32;
        const float* src = down + (size_t)e * FF * HD;
        float* dst = &g_W2T[e][0][0];
        #pragma unroll
        for (int i = 0; i < 32; i += 8)
            tile[ty + i][tx] = src[(size_t)(kt + ty + i) * HD + nt + tx];
        __syncthreads();
        #pragma unroll
        for (int i = 0; i < 32; i += 8)
            dst[(size_t)(nt + ty + i) * FF + kt + tx] = tf32r(tile[tx][ty + i]);
    }
}

// ======================= K1: router + x tf32-rounding =======================
__global__ void __launch_bounds__(256) k_router(
    const float* __restrict__ x, const float* __restrict__ gw,
    const int* __restrict__ tmod, const int* __restrict__ emod)
{
    __shared__ float sgw[NE * HD];
    for (int i = threadIdx.x; i < NE * HD / 4; i += blockDim.x)
        *(float4*)&sgw[i * 4] = ((const float4*)gw)[i];
    __syncthreads();

    int warp = threadIdx.x >> 5, lane = threadIdx.x & 31;
    int t = blockIdx.x * 8 + warp;
    if (t >= BS) return;

    const float4* xr = (const float4*)(x + (size_t)t * HD);
    float4* xo = (float4*)&g_xr[t][0];
    float acc[NE];
    #pragma unroll
    for (int e = 0; e < NE; e++) acc[e] = 0.f;
    #pragma unroll
    for (int i = 0; i < 8; i++) {
        int q = lane + i * 32;
        float4 xv = xr[q];
        float4 rv;
        rv.x = tf32r(xv.x); rv.y = tf32r(xv.y); rv.z = tf32r(xv.z); rv.w = tf32r(xv.w);
        xo[q] = rv;
        #pragma unroll
        for (int e = 0; e < NE; e++) {
            const float4 wv = *(const float4*)&sgw[e * HD + q * 4];
            acc[e] = fmaf(xv.x, wv.x, acc[e]);
            acc[e] = fmaf(xv.y, wv.y, acc[e]);
            acc[e] = fmaf(xv.z, wv.z, acc[e]);
            acc[e] = fmaf(xv.w, wv.w, acc[e]);
        }
    }
    #pragma unroll
    for (int e = 0; e < NE; e++) {
        #pragma unroll
        for (int o = 16; o > 0; o >>= 1) acc[e] += __shfl_xor_sync(0xffffffffu, acc[e], o);
    }
    if (lane == 0) {
        float m = acc[0];
        #pragma unroll
        for (int e = 1; e < NE; e++) m = fmaxf(m, acc[e]);
        float p[NE], s = 0.f;
        #pragma unroll
        for (int e = 0; e < NE; e++) { p[e] = __expf(acc[e] - m); s += p[e]; }
        float inv = 1.f / s;
        #pragma unroll
        for (int e = 0; e < NE; e++) p[e] *= inv;
        int i1 = 0; float m1 = p[0];
        #pragma unroll
        for (int e = 1; e < NE; e++) if (p[e] > m1) { m1 = p[e]; i1 = e; }
        int i2 = -1; float m2 = -1.f;
        #pragma unroll
        for (int e = 0; e < NE; e++) if (e != i1 && p[e] > m2) { m2 = p[e]; i2 = e; }
        float inv2 = 1.f / (m1 + m2);
        g_sel[t][0] = i1; g_sel[t][1] = i2;
        g_rw[t][0] = m1 * inv2; g_rw[t][1] = m2 * inv2;
        int tm = tmod[t];
        int sel2[2] = { i1, i2 };
        #pragma unroll
        for (int k = 0; k < 2; k++) {
            int e = sel2[k];
            int em = emod[e];
            if (tm != 0 && em != 0) {
                atomicAdd(&g_valid_cnt[e], 1);
                if (tm * em == -1) atomicAdd(&g_mis_cnt[e], 1);
            }
        }
    }
}

// ======================= K2: assign =======================
__global__ void k_assign(const int* __restrict__ emod) {
    int t = blockIdx.x * blockDim.x + threadIdx.x;
    if (t >= BS) return;
    bool skip[NE];
    #pragma unroll
    for (int e = 0; e < NE; e++) {
        int vc = g_valid_cnt[e], mc = g_mis_cnt[e];
        skip[e] = (vc > 0) && (mc == vc) && (emod[e] != 0);
    }
    int s0 = g_sel[t][0], s1 = g_sel[t][1];
    float w0 = g_rw[t][0], w1 = g_rw[t][1];
    if (skip[s0]) w0 = 0.f;
    if (skip[s1]) w1 = 0.f;
    float sum = w0 + w1;
    if (sum > 0.f) { float inv = 1.f / fmaxf(sum, EPSV); w0 *= inv; w1 *= inv; }
    g_wfinal[t][0] = w0; g_wfinal[t][1] = w1;
    if (w0 > 0.f) {
        int p = atomicAdd(&g_expert_cnt[s0], 1);
        g_expert_tok[s0][p] = t * 2;     g_expert_w[s0][p] = w0;
    }
    if (w1 > 0.f) {
        int p = atomicAdd(&g_expert_cnt[s1], 1);
        g_expert_tok[s1][p] = t * 2 + 1; g_expert_w[s1][p] = w1;
    }
}

// ======================= K5: GEMM1 (fused gather), warp tile 32x64 =======================
__global__ void __launch_bounds__(256, 2) k_mma1() {
    int e = blockIdx.z;
    int count = g_expert_cnt[e];
    int m0 = blockIdx.y * 128;
    if (m0 >= count) return;
    int f0 = blockIdx.x * 64;

    extern __shared__ char sm[];
    unsigned sb = smem_u32(sm);
    int tid = threadIdx.x, lane = tid & 31, w = tid >> 5;
    int wm = w & 3, wn = w >> 2;

    int* ts = (int*)sm;
    if (tid < 128) {
        int s = m0 + tid;
        ts[tid] = (s < count) ? (g_expert_tok[e][s] >> 1) : 0;
    }
    __syncthreads();

    const float* Xb = &g_xr[0][0];
    const float* Wb = &g_W1T[e][0][0];

    unsigned ga_off[4]; const float* gb[4]; unsigned soff[4];
    #pragma unroll
    for (int i = 0; i < 4; i++) {
        int idx = tid + i * 256;
        int r = idx >> 3, c = idx & 7;
        ga_off[i] = (unsigned)ts[r] * HD + c * 4;
        int bh = r >> 6, l = r & 63;
        int col = f0 + bh * 32 + (l & 31);
        int rowg = col + ((l & 32) ? 512 : 0);
        gb[i] = Wb + (size_t)rowg * HD + c * 4;
        soff[i] = r * 128 + ((c ^ (r & 7)) << 4);
    }

    float acc[2][8][4];
    #pragma unroll
    for (int h = 0; h < 2; h++)
        #pragma unroll
        for (int f = 0; f < 8; f++)
            #pragma unroll
            for (int q = 0; q < 4; q++) acc[h][f][q] = 0.f;

    int l7 = lane & 7, hi = lane >> 4, bsel = (lane >> 3) & 3;
    unsigned arow = sb + (wm * 32 + (lane & 15)) * 128;
    unsigned brow = sb + (wn * 64 + (lane & 7)) * 128;

    #pragma unroll
    for (int i = 0; i < 4; i++) {
        CP16(sb + SMM_A(0) + soff[i], Xb + ga_off[i]);
        CP16(sb + SMM_B(0) + soff[i], gb[i]);
    }
    CPCOMMIT();

    const int NK = HD / 32;
    for (int kb = 0; kb < NK; kb++) {
        int s = kb & 1;
        if (kb + 1 < NK) {
            int ns = s ^ 1;
            #pragma unroll
            for (int i = 0; i < 4; i++) {
                CP16(sb + SMM_A(ns) + soff[i], Xb + ga_off[i] + (kb + 1) * 32);
                CP16(sb + SMM_B(ns) + soff[i], gb[i] + (kb + 1) * 32);
            }
            CPCOMMIT();
            CPWAIT(1);
        } else {
            CPWAIT(0);
        }
        __syncthreads();

        unsigned sA = arow + SMM_A(s);
        unsigned sB = brow + SMM_B(s);
        #pragma unroll
        for (int kh = 0; kh < 2; kh++) {
            unsigned c0 = (((4 * kh + 0 + hi) ^ l7) << 4);
            unsigned c1 = (((4 * kh + 2 + hi) ^ l7) << 4);
            unsigned a0, a1, a2, a3, a4, a5, a6, a7;
            unsigned a8, a9, a10, a11, a12, a13, a14, a15;
            LDSM4(a0, a1, a2, a3, sA + c0);
            LDSM4(a4, a5, a6, a7, sA + c1);
            LDSM4(a8, a9, a10, a11, sA + 2048 + c0);
            LDSM4(a12, a13, a14, a15, sA + 2048 + c1);
            unsigned cb = (((4 * kh + bsel) ^ l7) << 4);
            #pragma unroll
            for (int f = 0; f < 8; f++) {
                unsigned b0, b1, b2, b3;
                LDSM4(b0, b1, b2, b3, sB + f * 1024 + cb);
                MMA8(acc[0][f], a0, a1, a2, a3, b0, b1);
                MMA8(acc[0][f], a4, a5, a6, a7, b2, b3);
                MMA8(acc[1][f], a8, a9, a10, a11, b0, b1);
                MMA8(acc[1][f], a12, a13, a14, a15, b2, b3);
            }
        }
        __syncthreads();
    }

    // epilogue: silu(g)*u — frag f (g, f<4) pairs with f+4 (u), same column, same thread
    int p = lane & 3, rlo = lane >> 2;
    #pragma unroll
    for (int h = 0; h < 2; h++) {
        int slot0 = m0 + wm * 32 + h * 16 + rlo;
        int slot1 = slot0 + 8;
        #pragma unroll
        for (int f = 0; f < 4; f++) {
            int j = f0 + wn * 32 + f * 8 + 2 * p;
            if (slot0 < count) {
                float g0 = acc[h][f][0], g1 = acc[h][f][1];
                float u0 = acc[h][f + 4][0], u1 = acc[h][f + 4][1];
                float v0 = tf32r(g0 / (1.f + __expf(-g0)) * u0);
                float v1 = tf32r(g1 / (1.f + __expf(-g1)) * u1);
                *(float2*)&g_act[e][slot0][j] = make_float2(v0, v1);
            }
            if (slot1 < count) {
                float g0 = acc[h][f][2], g1 = acc[h][f][3];
                float u0 = acc[h][f + 4][2], u1 = acc[h][f + 4][3];
                float v0 = tf32r(g0 / (1.f + __expf(-g0)) * u0);
                float v1 = tf32r(g1 / (1.f + __expf(-g1)) * u1);
                *(float2*)&g_act[e][slot1][j] = make_float2(v0, v1);
            }
        }
    }
}

// ======================= K6: GEMM2, warp tile 32x64, weighted scatter =======================
__global__ void __launch_bounds__(256, 2) k_mma2() {
    int e = blockIdx.z;
    int count = g_expert_cnt[e];
    int m0 = blockIdx.y * 128;
    if (m0 >= count) return;
    int n0 = blockIdx.x * 128;

    extern __shared__ char sm[];
    unsigned sb = smem_u32(sm);
    int tid = threadIdx.x, lane = tid & 31, w = tid >> 5;
    int wm = w & 3, wn = w >> 2;

    int*   tsp = (int*)sm;
    float* tw  = (float*)(sm + 512);
    if (tid < 128) {
        int s = m0 + tid;
        tsp[tid] = (s < count) ? g_expert_tok[e][s] : -1;
        tw[tid]  = (s < count) ? g_expert_w[e][s] : 0.f;
    }
    __syncthreads();

    const float* Ab = &g_act[e][m0][0];
    const float* Wb = &g_W2T[e][n0][0];

    const float* ga[4]; const float* gb[4]; unsigned soff[4];
    #pragma unroll
    for (int i = 0; i < 4; i++) {
        int idx = tid + i * 256;
        int r = idx >> 3, c = idx & 7;
        ga[i] = Ab + (size_t)r * FF + c * 4;
        gb[i] = Wb + (size_t)r * FF + c * 4;
        soff[i] = r * 128 + ((c ^ (r & 7)) << 4);
    }

    float acc[2][8][4];
    #pragma unroll
    for (int h = 0; h < 2; h++)
        #pragma unroll
        for (int f = 0; f < 8; f++)
            #pragma unroll
            for (int q = 0; q < 4; q++) acc[h][f][q] = 0.f;

    int l7 = lane & 7, hi = lane >> 4, bsel = (lane >> 3) & 3;
    unsigned arow = sb + (wm * 32 + (lane & 15)) * 128;
    unsigned brow = sb + (wn * 64 + (lane & 7)) * 128;

    #pragma unroll
    for (int i = 0; i < 4; i++) {
        CP16(sb + SMM_A(0) + soff[i], ga[i]);
        CP16(sb + SMM_B(0) + soff[i], gb[i]);
    }
    CPCOMMIT();

    const int NK = FF / 32;
    for (int kb = 0; kb < NK; kb++) {
        int s = kb & 1;
        if (kb + 1 < NK) {
            int ns = s ^ 1;
            #pragma unroll
            for (int i = 0; i < 4; i++) {
                CP16(sb + SMM_A(ns) + soff[i], ga[i] + (kb + 1) * 32);
                CP16(sb + SMM_B(ns) + soff[i], gb[i] + (kb + 1) * 32);
            }
            CPCOMMIT();
            CPWAIT(1);
        } else {
            CPWAIT(0);
        }
        __syncthreads();

        unsigned sA = arow + SMM_A(s);
        unsigned sB = brow + SMM_B(s);
        #pragma unroll
        for (int kh = 0; kh < 2; kh++) {
            unsigned c0 = (((4 * kh + 0 + hi) ^ l7) << 4);
            unsigned c1 = (((4 * kh + 2 + hi) ^ l7) << 4);
            unsigned a0, a1, a2, a3, a4, a5, a6, a7;
            unsigned a8, a9, a10, a11, a12, a13, a14, a15;
            LDSM4(a0, a1, a2, a3, sA + c0);
            LDSM4(a4, a5, a6, a7, sA + c1);
            LDSM4(a8, a9, a10, a11, sA + 2048 + c0);
            LDSM4(a12, a13, a14, a15, sA + 2048 + c1);
            unsigned cb = (((4 * kh + bsel) ^ l7) << 4);
            #pragma unroll
            for (int f = 0; f < 8; f++) {
                unsigned b0, b1, b2, b3;
                LDSM4(b0, b1, b2, b3, sB + f * 1024 + cb);
                MMA8(acc[0][f], a0, a1, a2, a3, b0, b1);
                MMA8(acc[0][f], a4, a5, a6, a7, b2, b3);
                MMA8(acc[1][f], a8, a9, a10, a11, b0, b1);
                MMA8(acc[1][f], a12, a13, a14, a15, b2, b3);
            }
        }
        __syncthreads();
    }

    // epilogue: weighted scatter (acc[h] covers warp rows h*16 .. h*16+15)
    int p = lane & 3, rlo = lane >> 2;
    #pragma unroll
    for (int h = 0; h < 2; h++) {
        int r0i = wm * 32 + h * 16 + rlo;
        int r1i = r0i + 8;
        int pk0 = tsp[r0i], pk1 = tsp[r1i];
        float wt0 = tw[r0i], wt1 = tw[r1i];
        #pragma unroll
        for (int f = 0; f < 8; f++) {
            int j = n0 + wn * 64 + f * 8 + 2 * p;
            if (pk0 >= 0) {
                float* dst = &g_partial[0][0][0] + (size_t)pk0 * HD + j;
                *(float2*)dst = make_float2(acc[h][f][0] * wt0, acc[h][f][1] * wt0);
            }
            if (pk1 >= 0) {
                float* dst = &g_partial[0][0][0] + (size_t)pk1 * HD + j;
                *(float2*)dst = make_float2(acc[h][f][2] * wt1, acc[h][f][3] * wt1);
            }
        }
    }
}

// ======================= K7: combine =======================
__global__ void k_combine(float* __restrict__ out) {
    int i = blockIdx.x * blockDim.x + threadIdx.x;
    if (i >= BS * HD / 4) return;
    int t = i >> 8;
    int c = i & 255;
    float w0 = g_wfinal[t][0], w1 = g_wfinal[t][1];
    float4 r = make_float4(0.f, 0.f, 0.f, 0.f);
    if (w0 > 0.f) {
        float4 a = *(const float4*)&g_partial[t][0][c * 4];
        r.x += a.x; r.y += a.y; r.z += a.z; r.w += a.w;
    }
    if (w1 > 0.f) {
        float4 b = *(const float4*)&g_partial[t][1][c * 4];
        r.x += b.x; r.y += b.y; r.z += b.z; r.w += b.w;
    }
    ((float4*)out)[i] = r;
}

// ======================= launch =======================
extern "C" void kernel_launch(void* const* d_in, const int* in_sizes, int n_in,
                              void* d_out, int out_size)
{
    const float* x    = (const float*)d_in[0];
    const float* gw   = (const float*)d_in[1];
    const float* gup  = (const float*)d_in[2];
    const float* down = (const float*)d_in[3];
    const int*   tmod = (const int*)d_in[4];
    const int*   emod = (const int*)d_in[5];
    float* out = (float*)d_out;

    cudaFuncSetAttribute(k_mma1, cudaFuncAttributeMaxDynamicSharedMemorySize, SMM_BYTES);
    cudaFuncSetAttribute(k_mma2, cudaFuncAttributeMaxDynamicSharedMemorySize, SMM_BYTES);

    k_prep<<<dim3(32, 48, NE), dim3(32, 8)>>>(gup, down);
    k_router<<<256, 256>>>(x, gw, tmod, emod);
    k_assign<<<8, 256>>>(emod);
    k_mma1<<<dim3(8, 16, NE), 256, SMM_BYTES>>>();
    k_mma2<<<dim3(8, 16, NE), 256, SMM_BYTES>>>();
    k_combine<<<(BS * HD / 4 + 255) / 256, 256>>>(out);
}

// round 7
// speedup vs baseline: 5.7024x; 1.5697x over previous
#include <cuda_runtime.h>
#include <cuda_fp16.h>

#define BS   2048
#define HD   1024
#define NE   8
#define FF   512
#define TWOF 1024
#define EPSV 1e-9f

// ======================= device scratch =======================
__device__ int    g_valid_cnt[NE];
__device__ int    g_mis_cnt[NE];
__device__ int    g_expert_cnt[NE];
__device__ int    g_expert_tok[NE][BS];     // packed token*2 + k
__device__ float  g_expert_w[NE][BS];
__device__ int    g_sel[BS][2];
__device__ float  g_rw[BS][2];
__device__ float  g_wfinal[BS][2];
__device__ __half g_xr[BS][HD];             // fp16 x (4 MB)
__device__ __half g_W1T[NE][TWOF][HD];      // gate_up^T fp16 (16.8 MB)
__device__ __half g_W2T[NE][HD][FF];        // down^T fp16 (8.4 MB)
__device__ __half g_act[NE][BS][FF];        // silu(g)*u fp16 (16.8 MB)
__device__ float  g_partial[BS][2][HD];     // weighted partials fp32

// ======================= PTX helpers =======================
__device__ __forceinline__ unsigned smem_u32(const void* p) {
    unsigned a;
    asm("{ .reg .u64 t; cvta.to.shared.u64 t, %1; cvt.u32.u64 %0, t; }" : "=r"(a) : "l"(p));
    return a;
}
#define CP16(s, g) asm volatile("cp.async.cg.shared.global [%0], [%1], 16;" :: "r"(s), "l"(g))
#define CPCOMMIT() asm volatile("cp.async.commit_group;" ::: "memory")
#define CPWAIT(n)  asm volatile("cp.async.wait_group %0;" :: "n"(n) : "memory")
#define LDSM4(r0, r1, r2, r3, a) \
    asm volatile("ldmatrix.sync.aligned.m8n8.x4.shared.b16 {%0,%1,%2,%3}, [%4];" \
        : "=r"(r0), "=r"(r1), "=r"(r2), "=r"(r3) : "r"(a))
#define MMAH(c, a0, a1, a2, a3, b0, b1) \
    asm volatile("mma.sync.aligned.m16n8k16.row.col.f32.f16.f16.f32 " \
        "{%0,%1,%2,%3}, {%4,%5,%6,%7}, {%8,%9}, {%0,%1,%2,%3};" \
        : "+f"((c)[0]), "+f"((c)[1]), "+f"((c)[2]), "+f"((c)[3]) \
        : "r"(a0), "r"(a1), "r"(a2), "r"(a3), "r"(b0), "r"(b1))

// dynamic smem: [0,512) tsp ints, [512,1024) tw floats,
// stage = A(16KB) + B(16KB); tiles are 128 rows x 64 halves = 128B/row
#define SMH_A(s) (1024 + (s) * 32768)
#define SMH_B(s) (1024 + (s) * 32768 + 16384)
#define SMH_BYTES (1024 + 2 * 32768)   // 66560

// ======================= K_prep: transposes -> fp16 + counter zero =======================
__global__ void __launch_bounds__(256) k_prep(
    const float* __restrict__ gup, const float* __restrict__ down)
{
    __shared__ float tile[32][33];
    int e = blockIdx.z;
    int tx = threadIdx.x, ty = threadIdx.y;
    if (blockIdx.x == 0 && blockIdx.y == 0 && e == 0 && ty == 0 && tx < NE) {
        g_valid_cnt[tx] = 0; g_mis_cnt[tx] = 0; g_expert_cnt[tx] = 0;
    }
    if (blockIdx.y < 32) {
        int kt = blockIdx.x * 32, nt = blockIdx.y * 32;
        const float* src = gup + (size_t)e * HD * TWOF;
        __half* dst = &g_W1T[e][0][0];
        #pragma unroll
        for (int i = 0; i < 32; i += 8)
            tile[ty + i][tx] = src[(size_t)(kt + ty + i) * TWOF + nt + tx];
        __syncthreads();
        #pragma unroll
        for (int i = 0; i < 32; i += 8)
            dst[(size_t)(nt + ty + i) * HD + kt + tx] = __float2half_rn(tile[tx][ty + i]);
    } else {
        int kt = (blockIdx.y - 32) * 32, nt = blockIdx.x * 32;
        const float* src = down + (size_t)e * FF * HD;
        __half* dst = &g_W2T[e][0][0];
        #pragma unroll
        for (int i = 0; i < 32; i += 8)
            tile[ty + i][tx] = src[(size_t)(kt + ty + i) * HD + nt + tx];
        __syncthreads();
        #pragma unroll
        for (int i = 0; i < 32; i += 8)
            dst[(size_t)(nt + ty + i) * FF + kt + tx] = __float2half_rn(tile[tx][ty + i]);
    }
}

// ======================= K1: router + x -> fp16 =======================
__global__ void __launch_bounds__(256) k_router(
    const float* __restrict__ x, const float* __restrict__ gw,
    const int* __restrict__ tmod, const int* __restrict__ emod)
{
    __shared__ float sgw[NE * HD];
    for (int i = threadIdx.x; i < NE * HD / 4; i += blockDim.x)
        *(float4*)&sgw[i * 4] = ((const float4*)gw)[i];
    __syncthreads();

    int warp = threadIdx.x >> 5, lane = threadIdx.x & 31;
    int t = blockIdx.x * 8 + warp;
    if (t >= BS) return;

    const float4* xr = (const float4*)(x + (size_t)t * HD);
    __half2* xo = (__half2*)&g_xr[t][0];
    float acc[NE];
    #pragma unroll
    for (int e = 0; e < NE; e++) acc[e] = 0.f;
    #pragma unroll
    for (int i = 0; i < 8; i++) {
        int q = lane + i * 32;
        float4 xv = xr[q];
        xo[q * 2 + 0] = __floats2half2_rn(xv.x, xv.y);
        xo[q * 2 + 1] = __floats2half2_rn(xv.z, xv.w);
        #pragma unroll
        for (int e = 0; e < NE; e++) {
            const float4 wv = *(const float4*)&sgw[e * HD + q * 4];
            acc[e] = fmaf(xv.x, wv.x, acc[e]);
            acc[e] = fmaf(xv.y, wv.y, acc[e]);
            acc[e] = fmaf(xv.z, wv.z, acc[e]);
            acc[e] = fmaf(xv.w, wv.w, acc[e]);
        }
    }
    #pragma unroll
    for (int e = 0; e < NE; e++) {
        #pragma unroll
        for (int o = 16; o > 0; o >>= 1) acc[e] += __shfl_xor_sync(0xffffffffu, acc[e], o);
    }
    if (lane == 0) {
        float m = acc[0];
        #pragma unroll
        for (int e = 1; e < NE; e++) m = fmaxf(m, acc[e]);
        float p[NE], s = 0.f;
        #pragma unroll
        for (int e = 0; e < NE; e++) { p[e] = __expf(acc[e] - m); s += p[e]; }
        float inv = 1.f / s;
        #pragma unroll
        for (int e = 0; e < NE; e++) p[e] *= inv;
        int i1 = 0; float m1 = p[0];
        #pragma unroll
        for (int e = 1; e < NE; e++) if (p[e] > m1) { m1 = p[e]; i1 = e; }
        int i2 = -1; float m2 = -1.f;
        #pragma unroll
        for (int e = 0; e < NE; e++) if (e != i1 && p[e] > m2) { m2 = p[e]; i2 = e; }
        float inv2 = 1.f / (m1 + m2);
        g_sel[t][0] = i1; g_sel[t][1] = i2;
        g_rw[t][0] = m1 * inv2; g_rw[t][1] = m2 * inv2;
        int tm = tmod[t];
        int sel2[2] = { i1, i2 };
        #pragma unroll
        for (int k = 0; k < 2; k++) {
            int e = sel2[k];
            int em = emod[e];
            if (tm != 0 && em != 0) {
                atomicAdd(&g_valid_cnt[e], 1);
                if (tm * em == -1) atomicAdd(&g_mis_cnt[e], 1);
            }
        }
    }
}

// ======================= K2: assign =======================
__global__ void k_assign(const int* __restrict__ emod) {
    int t = blockIdx.x * blockDim.x + threadIdx.x;
    if (t >= BS) return;
    bool skip[NE];
    #pragma unroll
    for (int e = 0; e < NE; e++) {
        int vc = g_valid_cnt[e], mc = g_mis_cnt[e];
        skip[e] = (vc > 0) && (mc == vc) && (emod[e] != 0);
    }
    int s0 = g_sel[t][0], s1 = g_sel[t][1];
    float w0 = g_rw[t][0], w1 = g_rw[t][1];
    if (skip[s0]) w0 = 0.f;
    if (skip[s1]) w1 = 0.f;
    float sum = w0 + w1;
    if (sum > 0.f) { float inv = 1.f / fmaxf(sum, EPSV); w0 *= inv; w1 *= inv; }
    g_wfinal[t][0] = w0; g_wfinal[t][1] = w1;
    if (w0 > 0.f) {
        int p = atomicAdd(&g_expert_cnt[s0], 1);
        g_expert_tok[s0][p] = t * 2;     g_expert_w[s0][p] = w0;
    }
    if (w1 > 0.f) {
        int p = atomicAdd(&g_expert_cnt[s1], 1);
        g_expert_tok[s1][p] = t * 2 + 1; g_expert_w[s1][p] = w1;
    }
}

// ======================= K5: GEMM1 fp16 (fused gather) + SiLU*u =======================
// CTA 128(M) x 128(B-rows: per-64 half = [32 g | 32 u]), BK=64, warp tile 32x64
__global__ void __launch_bounds__(256, 2) k_mma1() {
    int e = blockIdx.z;
    int count = g_expert_cnt[e];
    int m0 = blockIdx.y * 128;
    if (m0 >= count) return;
    int f0 = blockIdx.x * 64;

    extern __shared__ char sm[];
    unsigned sb = smem_u32(sm);
    int tid = threadIdx.x, lane = tid & 31, w = tid >> 5;
    int wm = w & 3, wn = w >> 2;

    int* ts = (int*)sm;
    if (tid < 128) {
        int s = m0 + tid;
        ts[tid] = (s < count) ? (g_expert_tok[e][s] >> 1) : 0;
    }
    __syncthreads();

    const __half* Xb = &g_xr[0][0];
    const __half* Wb = &g_W1T[e][0][0];

    // staging: 128 rows x 8 chunks of 16B (= 8 halves); 4 (row,chunk) per thread per tile
    unsigned ga_off[4]; const __half* gb[4]; unsigned soff[4];
    #pragma unroll
    for (int i = 0; i < 4; i++) {
        int idx = tid + i * 256;
        int r = idx >> 3, c = idx & 7;
        ga_off[i] = (unsigned)ts[r] * HD + c * 8;
        int bh = r >> 6, l = r & 63;
        int col = f0 + bh * 32 + (l & 31);
        int rowg = col + ((l & 32) ? 512 : 0);
        gb[i] = Wb + (size_t)rowg * HD + c * 8;
        soff[i] = r * 128 + ((c ^ (r & 7)) << 4);
    }

    float acc[2][8][4];
    #pragma unroll
    for (int h = 0; h < 2; h++)
        #pragma unroll
        for (int f = 0; f < 8; f++)
            #pragma unroll
            for (int q = 0; q < 4; q++) acc[h][f][q] = 0.f;

    // ldmatrix lane decomposition
    int l7 = lane & 7;
    int rA0 = (((lane >> 3) & 1) << 3) + l7;   // A: t&1 -> m-half, t>>1 -> k-chunk
    int cA  = lane >> 4;
    int rB0 = ((lane >> 4) << 3) + l7;         // B: t>>1 -> n-half, t&1 -> k-chunk
    int cB  = (lane >> 3) & 1;
    unsigned arow = (unsigned)(wm * 32 + rA0) * 128;
    unsigned brow0 = (unsigned)(wn * 64 + rB0) * 128;

    #pragma unroll
    for (int i = 0; i < 4; i++) {
        CP16(sb + SMH_A(0) + soff[i], Xb + ga_off[i]);
        CP16(sb + SMH_B(0) + soff[i], gb[i]);
    }
    CPCOMMIT();

    const int NK = HD / 64;
    for (int kb = 0; kb < NK; kb++) {
        int s = kb & 1;
        if (kb + 1 < NK) {
            int ns = s ^ 1;
            #pragma unroll
            for (int i = 0; i < 4; i++) {
                CP16(sb + SMH_A(ns) + soff[i], Xb + ga_off[i] + (kb + 1) * 64);
                CP16(sb + SMH_B(ns) + soff[i], gb[i] + (kb + 1) * 64);
            }
            CPCOMMIT();
            CPWAIT(1);
        } else {
            CPWAIT(0);
        }
        __syncthreads();

        unsigned sA = sb + SMH_A(s) + arow;
        unsigned sB = sb + SMH_B(s) + brow0;
        #pragma unroll
        for (int kc = 0; kc < 4; kc++) {
            unsigned aoff = (unsigned)(((kc * 2 + cA) ^ l7) << 4);
            unsigned boff = (unsigned)(((kc * 2 + cB) ^ l7) << 4);
            unsigned a0, a1, a2, a3, a4, a5, a6, a7;
            LDSM4(a0, a1, a2, a3, sA + aoff);
            LDSM4(a4, a5, a6, a7, sA + 2048 + aoff);
            #pragma unroll
            for (int fg = 0; fg < 4; fg++) {
                unsigned b0, b1, b2, b3;
                LDSM4(b0, b1, b2, b3, sB + fg * 2048 + boff);
                MMAH(acc[0][2 * fg],     a0, a1, a2, a3, b0, b1);
                MMAH(acc[0][2 * fg + 1], a0, a1, a2, a3, b2, b3);
                MMAH(acc[1][2 * fg],     a4, a5, a6, a7, b0, b1);
                MMAH(acc[1][2 * fg + 1], a4, a5, a6, a7, b2, b3);
            }
        }
        __syncthreads();
    }

    // epilogue: silu(g)*u — frag f (g, f<4) pairs with f+4 (u), same column, same thread
    int p = lane & 3, rlo = lane >> 2;
    #pragma unroll
    for (int h = 0; h < 2; h++) {
        int slot0 = m0 + wm * 32 + h * 16 + rlo;
        int slot1 = slot0 + 8;
        #pragma unroll
        for (int f = 0; f < 4; f++) {
            int j = f0 + wn * 32 + f * 8 + 2 * p;
            if (slot0 < count) {
                float g0 = acc[h][f][0], g1 = acc[h][f][1];
                float u0 = acc[h][f + 4][0], u1 = acc[h][f + 4][1];
                float v0 = g0 / (1.f + __expf(-g0)) * u0;
                float v1 = g1 / (1.f + __expf(-g1)) * u1;
                *(__half2*)&g_act[e][slot0][j] = __floats2half2_rn(v0, v1);
            }
            if (slot1 < count) {
                float g0 = acc[h][f][2], g1 = acc[h][f][3];
                float u0 = acc[h][f + 4][2], u1 = acc[h][f + 4][3];
                float v0 = g0 / (1.f + __expf(-g0)) * u0;
                float v1 = g1 / (1.f + __expf(-g1)) * u1;
                *(__half2*)&g_act[e][slot1][j] = __floats2half2_rn(v0, v1);
            }
        }
    }
}

// ======================= K6: GEMM2 fp16, weighted scatter =======================
__global__ void __launch_bounds__(256, 2) k_mma2() {
    int e = blockIdx.z;
    int count = g_expert_cnt[e];
    int m0 = blockIdx.y * 128;
    if (m0 >= count) return;
    int n0 = blockIdx.x * 128;

    extern __shared__ char sm[];
    unsigned sb = smem_u32(sm);
    int tid = threadIdx.x, lane = tid & 31, w = tid >> 5;
    int wm = w & 3, wn = w >> 2;

    int*   tsp = (int*)sm;
    float* tw  = (float*)(sm + 512);
    if (tid < 128) {
        int s = m0 + tid;
        tsp[tid] = (s < count) ? g_expert_tok[e][s] : -1;
        tw[tid]  = (s < count) ? g_expert_w[e][s] : 0.f;
    }
    __syncthreads();

    const __half* Ab = &g_act[e][m0][0];
    const __half* Wb = &g_W2T[e][n0][0];

    const __half* ga[4]; const __half* gb[4]; unsigned soff[4];
    #pragma unroll
    for (int i = 0; i < 4; i++) {
        int idx = tid + i * 256;
        int r = idx >> 3, c = idx & 7;
        ga[i] = Ab + (size_t)r * FF + c * 8;
        gb[i] = Wb + (size_t)r * FF + c * 8;
        soff[i] = r * 128 + ((c ^ (r & 7)) << 4);
    }

    float acc[2][8][4];
    #pragma unroll
    for (int h = 0; h < 2; h++)
        #pragma unroll
        for (int f = 0; f < 8; f++)
            #pragma unroll
            for (int q = 0; q < 4; q++) acc[h][f][q] = 0.f;

    int l7 = lane & 7;
    int rA0 = (((lane >> 3) & 1) << 3) + l7;
    int cA  = lane >> 4;
    int rB0 = ((lane >> 4) << 3) + l7;
    int cB  = (lane >> 3) & 1;
    unsigned arow = (unsigned)(wm * 32 + rA0) * 128;
    unsigned brow0 = (unsigned)(wn * 64 + rB0) * 128;

    #pragma unroll
    for (int i = 0; i < 4; i++) {
        CP16(sb + SMH_A(0) + soff[i], ga[i]);
        CP16(sb + SMH_B(0) + soff[i], gb[i]);
    }
    CPCOMMIT();

    const int NK = FF / 64;
    for (int kb = 0; kb < NK; kb++) {
        int s = kb & 1;
        if (kb + 1 < NK) {
            int ns = s ^ 1;
            #pragma unroll
            for (int i = 0; i < 4; i++) {
                CP16(sb + SMH_A(ns) + soff[i], ga[i] + (kb + 1) * 64);
                CP16(sb + SMH_B(ns) + soff[i], gb[i] + (kb + 1) * 64);
            }
            CPCOMMIT();
            CPWAIT(1);
        } else {
            CPWAIT(0);
        }
        __syncthreads();

        unsigned sA = sb + SMH_A(s) + arow;
        unsigned sB = sb + SMH_B(s) + brow0;
        #pragma unroll
        for (int kc = 0; kc < 4; kc++) {
            unsigned aoff = (unsigned)(((kc * 2 + cA) ^ l7) << 4);
            unsigned boff = (unsigned)(((kc * 2 + cB) ^ l7) << 4);
            unsigned a0, a1, a2, a3, a4, a5, a6, a7;
            LDSM4(a0, a1, a2, a3, sA + aoff);
            LDSM4(a4, a5, a6, a7, sA + 2048 + aoff);
            #pragma unroll
            for (int fg = 0; fg < 4; fg++) {
                unsigned b0, b1, b2, b3;
                LDSM4(b0, b1, b2, b3, sB + fg * 2048 + boff);
                MMAH(acc[0][2 * fg],     a0, a1, a2, a3, b0, b1);
                MMAH(acc[0][2 * fg + 1], a0, a1, a2, a3, b2, b3);
                MMAH(acc[1][2 * fg],     a4, a5, a6, a7, b0, b1);
                MMAH(acc[1][2 * fg + 1], a4, a5, a6, a7, b2, b3);
            }
        }
        __syncthreads();
    }

    // epilogue: weighted scatter (acc[h] covers warp rows h*16 .. h*16+15)
    int p = lane & 3, rlo = lane >> 2;
    #pragma unroll
    for (int h = 0; h < 2; h++) {
        int r0i = wm * 32 + h * 16 + rlo;
        int r1i = r0i + 8;
        int pk0 = tsp[r0i], pk1 = tsp[r1i];
        float wt0 = tw[r0i], wt1 = tw[r1i];
        #pragma unroll
        for (int f = 0; f < 8; f++) {
            int j = n0 + wn * 64 + f * 8 + 2 * p;
            if (pk0 >= 0) {
                float* dst = &g_partial[0][0][0] + (size_t)pk0 * HD + j;
                *(float2*)dst = make_float2(acc[h][f][0] * wt0, acc[h][f][1] * wt0);
            }
            if (pk1 >= 0) {
                float* dst = &g_partial[0][0][0] + (size_t)pk1 * HD + j;
                *(float2*)dst = make_float2(acc[h][f][2] * wt1, acc[h][f][3] * wt1);
            }
        }
    }
}

// ======================= K7: combine =======================
__global__ void k_combine(float* __restrict__ out) {
    int i = blockIdx.x * blockDim.x + threadIdx.x;
    if (i >= BS * HD / 4) return;
    int t = i >> 8;
    int c = i & 255;
    float w0 = g_wfinal[t][0], w1 = g_wfinal[t][1];
    float4 r = make_float4(0.f, 0.f, 0.f, 0.f);
    if (w0 > 0.f) {
        float4 a = *(const float4*)&g_partial[t][0][c * 4];
        r.x += a.x; r.y += a.y; r.z += a.z; r.w += a.w;
    }
    if (w1 > 0.f) {
        float4 b = *(const float4*)&g_partial[t][1][c * 4];
        r.x += b.x; r.y += b.y; r.z += b.z; r.w += b.w;
    }
    ((float4*)out)[i] = r;
}

// ======================= launch =======================
extern "C" void kernel_launch(void* const* d_in, const int* in_sizes, int n_in,
                              void* d_out, int out_size)
{
    const float* x    = (const float*)d_in[0];
    const float* gw   = (const float*)d_in[1];
    const float* gup  = (const float*)d_in[2];
    const float* down = (const float*)d_in[3];
    const int*   tmod = (const int*)d_in[4];
    const int*   emod = (const int*)d_in[5];
    float* out = (float*)d_out;

    cudaFuncSetAttribute(k_mma1, cudaFuncAttributeMaxDynamicSharedMemorySize, SMH_BYTES);
    cudaFuncSetAttribute(k_mma2, cudaFuncAttributeMaxDynamicSharedMemorySize, SMH_BYTES);

    k_prep<<<dim3(32, 48, NE), dim3(32, 8)>>>(gup, down);
    k_router<<<256, 256>>>(x, gw, tmod, emod);
    k_assign<<<8, 256>>>(emod);
    k_mma1<<<dim3(8, 16, NE), 256, SMH_BYTES>>>();
    k_mma2<<<dim3(8, 16, NE), 256, SMH_BYTES>>>();
    k_combine<<<(BS * HD / 4 + 255) / 256, 256>>>(out);
}

// round 8
// speedup vs baseline: 5.8987x; 1.0344x over previous
#include <cuda_runtime.h>
#include <cuda_fp16.h>

#define BS   2048
#define HD   1024
#define NE   8
#define FF   512
#define TWOF 1024
#define EPSV 1e-9f

// ======================= device scratch =======================
__device__ int    g_valid_cnt[NE];
__device__ int    g_mis_cnt[NE];
__device__ int    g_expert_cnt[NE];
__device__ int    g_expert_tok[NE][BS];     // packed token*2 + k
__device__ float  g_expert_w[NE][BS];
__device__ int    g_sel[BS][2];
__device__ float  g_rw[BS][2];
__device__ __half g_xr[BS][HD];             // fp16 x (4 MB)
__device__ __half g_W1T[NE][TWOF][HD];      // gate_up^T fp16 (16.8 MB)
__device__ __half g_W2T[NE][HD][FF];        // down^T fp16 (8.4 MB)
__device__ __half g_act[NE][BS][FF];        // silu(g)*u fp16 (16.8 MB)

// ======================= PTX helpers =======================
__device__ __forceinline__ unsigned smem_u32(const void* p) {
    unsigned a;
    asm("{ .reg .u64 t; cvta.to.shared.u64 t, %1; cvt.u32.u64 %0, t; }" : "=r"(a) : "l"(p));
    return a;
}
#define CP16(s, g) asm volatile("cp.async.cg.shared.global [%0], [%1], 16;" :: "r"(s), "l"(g))
#define CPCOMMIT() asm volatile("cp.async.commit_group;" ::: "memory")
#define CPWAIT(n)  asm volatile("cp.async.wait_group %0;" :: "n"(n) : "memory")
#define LDSM4(r0, r1, r2, r3, a) \
    asm volatile("ldmatrix.sync.aligned.m8n8.x4.shared.b16 {%0,%1,%2,%3}, [%4];" \
        : "=r"(r0), "=r"(r1), "=r"(r2), "=r"(r3) : "r"(a))
#define MMAH(c, a0, a1, a2, a3, b0, b1) \
    asm volatile("mma.sync.aligned.m16n8k16.row.col.f32.f16.f16.f32 " \
        "{%0,%1,%2,%3}, {%4,%5,%6,%7}, {%8,%9}, {%0,%1,%2,%3};" \
        : "+f"((c)[0]), "+f"((c)[1]), "+f"((c)[2]), "+f"((c)[3]) \
        : "r"(a0), "r"(a1), "r"(a2), "r"(a3), "r"(b0), "r"(b1))

// dynamic smem: [0,512) tsp ints, [512,1024) tw floats, 3 stages x (A 16KB + B 16KB)
#define SMH_A(s) (1024 + (s) * 32768)
#define SMH_B(s) (1024 + (s) * 32768 + 16384)
#define SMH_BYTES (1024 + 3 * 32768)   // 99328

// ======================= K_prep: transposes -> fp16 + counter zero =======================
__global__ void __launch_bounds__(256) k_prep(
    const float* __restrict__ gup, const float* __restrict__ down)
{
    __shared__ float tile[32][33];
    int e = blockIdx.z;
    int tx = threadIdx.x, ty = threadIdx.y;
    if (blockIdx.x == 0 && blockIdx.y == 0 && e == 0 && ty == 0 && tx < NE) {
        g_valid_cnt[tx] = 0; g_mis_cnt[tx] = 0; g_expert_cnt[tx] = 0;
    }
    if (blockIdx.y < 32) {
        int kt = blockIdx.x * 32, nt = blockIdx.y * 32;
        const float* src = gup + (size_t)e * HD * TWOF;
        __half* dst = &g_W1T[e][0][0];
        #pragma unroll
        for (int i = 0; i < 32; i += 8)
            tile[ty + i][tx] = src[(size_t)(kt + ty + i) * TWOF + nt + tx];
        __syncthreads();
        #pragma unroll
        for (int i = 0; i < 32; i += 8)
            dst[(size_t)(nt + ty + i) * HD + kt + tx] = __float2half_rn(tile[tx][ty + i]);
    } else {
        int kt = (blockIdx.y - 32) * 32, nt = blockIdx.x * 32;
        const float* src = down + (size_t)e * FF * HD;
        __half* dst = &g_W2T[e][0][0];
        #pragma unroll
        for (int i = 0; i < 32; i += 8)
            tile[ty + i][tx] = src[(size_t)(kt + ty + i) * HD + nt + tx];
        __syncthreads();
        #pragma unroll
        for (int i = 0; i < 32; i += 8)
            dst[(size_t)(nt + ty + i) * FF + kt + tx] = __float2half_rn(tile[tx][ty + i]);
    }
}

// ======================= K1: router + x -> fp16 =======================
__global__ void __launch_bounds__(256) k_router(
    const float* __restrict__ x, const float* __restrict__ gw,
    const int* __restrict__ tmod, const int* __restrict__ emod)
{
    __shared__ float sgw[NE * HD];
    for (int i = threadIdx.x; i < NE * HD / 4; i += blockDim.x)
        *(float4*)&sgw[i * 4] = ((const float4*)gw)[i];
    __syncthreads();

    int warp = threadIdx.x >> 5, lane = threadIdx.x & 31;
    int t = blockIdx.x * 8 + warp;
    if (t >= BS) return;

    const float4* xr = (const float4*)(x + (size_t)t * HD);
    __half2* xo = (__half2*)&g_xr[t][0];
    float acc[NE];
    #pragma unroll
    for (int e = 0; e < NE; e++) acc[e] = 0.f;
    #pragma unroll
    for (int i = 0; i < 8; i++) {
        int q = lane + i * 32;
        float4 xv = xr[q];
        xo[q * 2 + 0] = __floats2half2_rn(xv.x, xv.y);
        xo[q * 2 + 1] = __floats2half2_rn(xv.z, xv.w);
        #pragma unroll
        for (int e = 0; e < NE; e++) {
            const float4 wv = *(const float4*)&sgw[e * HD + q * 4];
            acc[e] = fmaf(xv.x, wv.x, acc[e]);
            acc[e] = fmaf(xv.y, wv.y, acc[e]);
            acc[e] = fmaf(xv.z, wv.z, acc[e]);
            acc[e] = fmaf(xv.w, wv.w, acc[e]);
        }
    }
    #pragma unroll
    for (int e = 0; e < NE; e++) {
        #pragma unroll
        for (int o = 16; o > 0; o >>= 1) acc[e] += __shfl_xor_sync(0xffffffffu, acc[e], o);
    }
    if (lane == 0) {
        float m = acc[0];
        #pragma unroll
        for (int e = 1; e < NE; e++) m = fmaxf(m, acc[e]);
        float p[NE], s = 0.f;
        #pragma unroll
        for (int e = 0; e < NE; e++) { p[e] = __expf(acc[e] - m); s += p[e]; }
        float inv = 1.f / s;
        #pragma unroll
        for (int e = 0; e < NE; e++) p[e] *= inv;
        int i1 = 0; float m1 = p[0];
        #pragma unroll
        for (int e = 1; e < NE; e++) if (p[e] > m1) { m1 = p[e]; i1 = e; }
        int i2 = -1; float m2 = -1.f;
        #pragma unroll
        for (int e = 0; e < NE; e++) if (e != i1 && p[e] > m2) { m2 = p[e]; i2 = e; }
        float inv2 = 1.f / (m1 + m2);
        g_sel[t][0] = i1; g_sel[t][1] = i2;
        g_rw[t][0] = m1 * inv2; g_rw[t][1] = m2 * inv2;
        int tm = tmod[t];
        int sel2[2] = { i1, i2 };
        #pragma unroll
        for (int k = 0; k < 2; k++) {
            int e = sel2[k];
            int em = emod[e];
            if (tm != 0 && em != 0) {
                atomicAdd(&g_valid_cnt[e], 1);
                if (tm * em == -1) atomicAdd(&g_mis_cnt[e], 1);
            }
        }
    }
}

// ======================= K2: assign =======================
__global__ void k_assign(const int* __restrict__ emod) {
    int t = blockIdx.x * blockDim.x + threadIdx.x;
    if (t >= BS) return;
    bool skip[NE];
    #pragma unroll
    for (int e = 0; e < NE; e++) {
        int vc = g_valid_cnt[e], mc = g_mis_cnt[e];
        skip[e] = (vc > 0) && (mc == vc) && (emod[e] != 0);
    }
    int s0 = g_sel[t][0], s1 = g_sel[t][1];
    float w0 = g_rw[t][0], w1 = g_rw[t][1];
    if (skip[s0]) w0 = 0.f;
    if (skip[s1]) w1 = 0.f;
    float sum = w0 + w1;
    if (sum > 0.f) { float inv = 1.f / fmaxf(sum, EPSV); w0 *= inv; w1 *= inv; }
    if (w0 > 0.f) {
        int p = atomicAdd(&g_expert_cnt[s0], 1);
        g_expert_tok[s0][p] = t * 2;     g_expert_w[s0][p] = w0;
    }
    if (w1 > 0.f) {
        int p = atomicAdd(&g_expert_cnt[s1], 1);
        g_expert_tok[s1][p] = t * 2 + 1; g_expert_w[s1][p] = w1;
    }
}

// ======================= K3: zero output =======================
__global__ void k_zero_out(float4* __restrict__ out) {
    int i = blockIdx.x * blockDim.x + threadIdx.x;
    if (i < BS * HD / 4) out[i] = make_float4(0.f, 0.f, 0.f, 0.f);
}

// ======================= K5: GEMM1 fp16 (fused gather) + SiLU*u, 3-stage =======================
__global__ void __launch_bounds__(256, 2) k_mma1() {
    int e = blockIdx.z;
    int count = g_expert_cnt[e];
    int m0 = blockIdx.y * 128;
    if (m0 >= count) return;
    int f0 = blockIdx.x * 64;

    extern __shared__ char sm[];
    unsigned sb = smem_u32(sm);
    int tid = threadIdx.x, lane = tid & 31, w = tid >> 5;
    int wm = w & 3, wn = w >> 2;

    int* ts = (int*)sm;
    if (tid < 128) {
        int s = m0 + tid;
        ts[tid] = (s < count) ? (g_expert_tok[e][s] >> 1) : 0;
    }
    __syncthreads();

    const __half* Xb = &g_xr[0][0];
    const __half* Wb = &g_W1T[e][0][0];

    unsigned ga_off[4]; const __half* gb[4]; unsigned soff[4];
    #pragma unroll
    for (int i = 0; i < 4; i++) {
        int idx = tid + i * 256;
        int r = idx >> 3, c = idx & 7;
        ga_off[i] = (unsigned)ts[r] * HD + c * 8;
        int bh = r >> 6, l = r & 63;
        int col = f0 + bh * 32 + (l & 31);
        int rowg = col + ((l & 32) ? 512 : 0);
        gb[i] = Wb + (size_t)rowg * HD + c * 8;
        soff[i] = r * 128 + ((c ^ (r & 7)) << 4);
    }

    float acc[2][8][4];
    #pragma unroll
    for (int h = 0; h < 2; h++)
        #pragma unroll
        for (int f = 0; f < 8; f++)
            #pragma unroll
            for (int q = 0; q < 4; q++) acc[h][f][q] = 0.f;

    int l7 = lane & 7;
    int rA0 = (((lane >> 3) & 1) << 3) + l7;
    int cA  = lane >> 4;
    int rB0 = ((lane >> 4) << 3) + l7;
    int cB  = (lane >> 3) & 1;
    unsigned arow = (unsigned)(wm * 32 + rA0) * 128;
    unsigned brow0 = (unsigned)(wn * 64 + rB0) * 128;

    const int NK = HD / 64;
    // prologue: stages 0 and 1
    #pragma unroll
    for (int i = 0; i < 4; i++) {
        CP16(sb + SMH_A(0) + soff[i], Xb + ga_off[i]);
        CP16(sb + SMH_B(0) + soff[i], gb[i]);
    }
    CPCOMMIT();
    #pragma unroll
    for (int i = 0; i < 4; i++) {
        CP16(sb + SMH_A(1) + soff[i], Xb + ga_off[i] + 64);
        CP16(sb + SMH_B(1) + soff[i], gb[i] + 64);
    }
    CPCOMMIT();

    for (int kb = 0; kb < NK; kb++) {
        int s = kb % 3;
        if (kb >= NK - 1) { CPWAIT(0); } else { CPWAIT(1); }
        __syncthreads();
        if (kb + 2 < NK) {
            int ns = (kb + 2) % 3;
            #pragma unroll
            for (int i = 0; i < 4; i++) {
                CP16(sb + SMH_A(ns) + soff[i], Xb + ga_off[i] + (kb + 2) * 64);
                CP16(sb + SMH_B(ns) + soff[i], gb[i] + (kb + 2) * 64);
            }
            CPCOMMIT();
        }
        unsigned sA = sb + SMH_A(s) + arow;
        unsigned sB = sb + SMH_B(s) + brow0;
        #pragma unroll
        for (int kc = 0; kc < 4; kc++) {
            unsigned aoff = (unsigned)(((kc * 2 + cA) ^ l7) << 4);
            unsigned boff = (unsigned)(((kc * 2 + cB) ^ l7) << 4);
            unsigned a0, a1, a2, a3, a4, a5, a6, a7;
            LDSM4(a0, a1, a2, a3, sA + aoff);
            LDSM4(a4, a5, a6, a7, sA + 2048 + aoff);
            #pragma unroll
            for (int fg = 0; fg < 4; fg++) {
                unsigned b0, b1, b2, b3;
                LDSM4(b0, b1, b2, b3, sB + fg * 2048 + boff);
                MMAH(acc[0][2 * fg],     a0, a1, a2, a3, b0, b1);
                MMAH(acc[0][2 * fg + 1], a0, a1, a2, a3, b2, b3);
                MMAH(acc[1][2 * fg],     a4, a5, a6, a7, b0, b1);
                MMAH(acc[1][2 * fg + 1], a4, a5, a6, a7, b2, b3);
            }
        }
    }

    // epilogue: silu(g)*u — frag f (g, f<4) pairs with f+4 (u), same column, same thread
    int p = lane & 3, rlo = lane >> 2;
    #pragma unroll
    for (int h = 0; h < 2; h++) {
        int slot0 = m0 + wm * 32 + h * 16 + rlo;
        int slot1 = slot0 + 8;
        #pragma unroll
        for (int f = 0; f < 4; f++) {
            int j = f0 + wn * 32 + f * 8 + 2 * p;
            if (slot0 < count) {
                float g0 = acc[h][f][0], g1 = acc[h][f][1];
                float u0 = acc[h][f + 4][0], u1 = acc[h][f + 4][1];
                float v0 = g0 / (1.f + __expf(-g0)) * u0;
                float v1 = g1 / (1.f + __expf(-g1)) * u1;
                *(__half2*)&g_act[e][slot0][j] = __floats2half2_rn(v0, v1);
            }
            if (slot1 < count) {
                float g0 = acc[h][f][2], g1 = acc[h][f][3];
                float u0 = acc[h][f + 4][2], u1 = acc[h][f + 4][3];
                float v0 = g0 / (1.f + __expf(-g0)) * u0;
                float v1 = g1 / (1.f + __expf(-g1)) * u1;
                *(__half2*)&g_act[e][slot1][j] = __floats2half2_rn(v0, v1);
            }
        }
    }
}

// ======================= K6: GEMM2 fp16, 3-stage, weighted atomic accumulate =======================
__global__ void __launch_bounds__(256, 2) k_mma2(float* __restrict__ out) {
    int e = blockIdx.z;
    int count = g_expert_cnt[e];
    int m0 = blockIdx.y * 128;
    if (m0 >= count) return;
    int n0 = blockIdx.x * 128;

    extern __shared__ char sm[];
    unsigned sb = smem_u32(sm);
    int tid = threadIdx.x, lane = tid & 31, w = tid >> 5;
    int wm = w & 3, wn = w >> 2;

    int*   tsp = (int*)sm;
    float* tw  = (float*)(sm + 512);
    if (tid < 128) {
        int s = m0 + tid;
        tsp[tid] = (s < count) ? g_expert_tok[e][s] : -1;
        tw[tid]  = (s < count) ? g_expert_w[e][s] : 0.f;
    }
    __syncthreads();

    const __half* Ab = &g_act[e][m0][0];
    const __half* Wb = &g_W2T[e][n0][0];

    const __half* ga[4]; const __half* gb[4]; unsigned soff[4];
    #pragma unroll
    for (int i = 0; i < 4; i++) {
        int idx = tid + i * 256;
        int r = idx >> 3, c = idx & 7;
        ga[i] = Ab + (size_t)r * FF + c * 8;
        gb[i] = Wb + (size_t)r * FF + c * 8;
        soff[i] = r * 128 + ((c ^ (r & 7)) << 4);
    }

    float acc[2][8][4];
    #pragma unroll
    for (int h = 0; h < 2; h++)
        #pragma unroll
        for (int f = 0; f < 8; f++)
            #pragma unroll
            for (int q = 0; q < 4; q++) acc[h][f][q] = 0.f;

    int l7 = lane & 7;
    int rA0 = (((lane >> 3) & 1) << 3) + l7;
    int cA  = lane >> 4;
    int rB0 = ((lane >> 4) << 3) + l7;
    int cB  = (lane >> 3) & 1;
    unsigned arow = (unsigned)(wm * 32 + rA0) * 128;
    unsigned brow0 = (unsigned)(wn * 64 + rB0) * 128;

    const int NK = FF / 64;
    #pragma unroll
    for (int i = 0; i < 4; i++) {
        CP16(sb + SMH_A(0) + soff[i], ga[i]);
        CP16(sb + SMH_B(0) + soff[i], gb[i]);
    }
    CPCOMMIT();
    #pragma unroll
    for (int i = 0; i < 4; i++) {
        CP16(sb + SMH_A(1) + soff[i], ga[i] + 64);
        CP16(sb + SMH_B(1) + soff[i], gb[i] + 64);
    }
    CPCOMMIT();

    for (int kb = 0; kb < NK; kb++) {
        int s = kb % 3;
        if (kb >= NK - 1) { CPWAIT(0); } else { CPWAIT(1); }
        __syncthreads();
        if (kb + 2 < NK) {
            int ns = (kb + 2) % 3;
            #pragma unroll
            for (int i = 0; i < 4; i++) {
                CP16(sb + SMH_A(ns) + soff[i], ga[i] + (kb + 2) * 64);
                CP16(sb + SMH_B(ns) + soff[i], gb[i] + (kb + 2) * 64);
            }
            CPCOMMIT();
        }
        unsigned sA = sb + SMH_A(s) + arow;
        unsigned sB = sb + SMH_B(s) + brow0;
        #pragma unroll
        for (int kc = 0; kc < 4; kc++) {
            unsigned aoff = (unsigned)(((kc * 2 + cA) ^ l7) << 4);
            unsigned boff = (unsigned)(((kc * 2 + cB) ^ l7) << 4);
            unsigned a0, a1, a2, a3, a4, a5, a6, a7;
            LDSM4(a0, a1, a2, a3, sA + aoff);
            LDSM4(a4, a5, a6, a7, sA + 2048 + aoff);
            #pragma unroll
            for (int fg = 0; fg < 4; fg++) {
                unsigned b0, b1, b2, b3;
                LDSM4(b0, b1, b2, b3, sB + fg * 2048 + boff);
                MMAH(acc[0][2 * fg],     a0, a1, a2, a3, b0, b1);
                MMAH(acc[0][2 * fg + 1], a0, a1, a2, a3, b2, b3);
                MMAH(acc[1][2 * fg],     a4, a5, a6, a7, b0, b1);
                MMAH(acc[1][2 * fg + 1], a4, a5, a6, a7, b2, b3);
            }
        }
    }

    // epilogue: weighted atomic accumulate into out (out pre-zeroed; <=2 adds/address)
    int p = lane & 3, rlo = lane >> 2;
    #pragma unroll
    for (int h = 0; h < 2; h++) {
        int r0i = wm * 32 + h * 16 + rlo;
        int r1i = r0i + 8;
        int pk0 = tsp[r0i], pk1 = tsp[r1i];
        float wt0 = tw[r0i], wt1 = tw[r1i];
        #pragma unroll
        for (int f = 0; f < 8; f++) {
            int j = n0 + wn * 64 + f * 8 + 2 * p;
            if (pk0 >= 0) {
                float* dst = out + (size_t)(pk0 >> 1) * HD + j;
                atomicAdd(dst,     acc[h][f][0] * wt0);
                atomicAdd(dst + 1, acc[h][f][1] * wt0);
            }
            if (pk1 >= 0) {
                float* dst = out + (size_t)(pk1 >> 1) * HD + j;
                atomicAdd(dst,     acc[h][f][2] * wt1);
                atomicAdd(dst + 1, acc[h][f][3] * wt1);
            }
        }
    }
}

// ======================= launch =======================
extern "C" void kernel_launch(void* const* d_in, const int* in_sizes, int n_in,
                              void* d_out, int out_size)
{
    const float* x    = (const float*)d_in[0];
    const float* gw   = (const float*)d_in[1];
    const float* gup  = (const float*)d_in[2];
    const float* down = (const float*)d_in[3];
    const int*   tmod = (const int*)d_in[4];
    const int*   emod = (const int*)d_in[5];
    float* out = (float*)d_out;

    cudaFuncSetAttribute(k_mma1, cudaFuncAttributeMaxDynamicSharedMemorySize, SMH_BYTES);
    cudaFuncSetAttribute(k_mma2, cudaFuncAttributeMaxDynamicSharedMemorySize, SMH_BYTES);

    k_prep<<<dim3(32, 48, NE), dim3(32, 8)>>>(gup, down);
    k_router<<<256, 256>>>(x, gw, tmod, emod);
    k_assign<<<8, 256>>>(emod);
    k_zero_out<<<(BS * HD / 4 + 255) / 256, 256>>>((float4*)out);
    k_mma1<<<dim3(8, 16, NE), 256, SMH_BYTES>>>();
    k_mma2<<<dim3(8, 16, NE), 256, SMH_BYTES>>>(out);
}